// round 6
// baseline (speedup 1.0000x reference)
#include <cuda_runtime.h>
#include <math.h>

#define NPC 16384
#define NTC 131072
#define NFC 131072
#define EC  262144
#define BC  256
#define FULLMASK 0xffffffffu

// ---------------- device scratch ----------------
__device__ float g_xp[NPC * 64];
__device__ float g_xt[2][NTC * 64];     // ping-pong (fusion overwrites in-place otherwise)
__device__ float g_xf[2][NFC * 64];
__device__ float g_ap[NPC * 64];
// double-buffered attention scores (ping-pong by layer parity)
__device__ float g_ss_pt[2][NPC], g_ss_pf[2][NPC], g_sd_tp[2][NPC], g_sd_fp[2][NPC];
__device__ float g_ss_tp[2][NTC], g_sd_pt[2][NTC];
__device__ float g_ss_fp[2][NFC], g_sd_pf[2][NFC];
__device__ float g_wsv[5 * 4 * 64], g_wdv[5 * 4 * 64];
__device__ int g_rp_pt[NTC + 1], g_rp_pf[NFC + 1];
__device__ int g_rp_tp[NPC + 1], g_rp_fp[NPC + 1];
__device__ int g_cs_pt[EC], g_cs_tp[EC], g_cs_pf[EC], g_cs_fp[EC];
__device__ int g_cnt[4 * NTC];
__device__ float g_ra[NPC * 2];
__device__ float g_rep[BC * 576];
__device__ float g_h1[BC * 64], g_h2[BC * 64];

// ---------------- batched CSR build ----------------
__global__ void zero4(int* c) {
    int i = blockIdx.x * blockDim.x + threadIdx.x;
    if (i < 4 * NTC) c[i] = 0;
}

__global__ void hist4(const int* __restrict__ d0, const int* __restrict__ d1,
                      const int* __restrict__ d2, const int* __restrict__ d3,
                      int* __restrict__ cnt) {
    int t = blockIdx.y;
    const int* d = (t == 0) ? d0 : (t == 1) ? d1 : (t == 2) ? d2 : d3;
    int* c = cnt + t * NTC;
    int i = blockIdx.x * blockDim.x + threadIdx.x;
    if (i < EC) atomicAdd(&c[d[i]], 1);
}

__device__ void scan_body(const int* __restrict__ deg, int* __restrict__ rowptr,
                          int* __restrict__ rezero, int n) {
    __shared__ int warp_sums[32];
    __shared__ int s_carry;
    int tid = threadIdx.x;
    int lane = tid & 31, wid = tid >> 5;
    if (tid == 0) s_carry = 0;
    __syncthreads();
    for (int base = 0; base < n; base += 1024) {
        int i = base + tid;
        int v = (i < n) ? deg[i] : 0;
        int x = v;
        #pragma unroll
        for (int off = 1; off < 32; off <<= 1) {
            int y = __shfl_up_sync(FULLMASK, x, off);
            if (lane >= off) x += y;
        }
        if (lane == 31) warp_sums[wid] = x;
        __syncthreads();
        if (tid < 32) {
            int s = warp_sums[tid];
            #pragma unroll
            for (int off = 1; off < 32; off <<= 1) {
                int y = __shfl_up_sync(FULLMASK, s, off);
                if (tid >= off) s += y;
            }
            warp_sums[tid] = s;
        }
        __syncthreads();
        int incl = x + (wid ? warp_sums[wid - 1] : 0);
        if (i < n) { rowptr[i] = s_carry + incl - v; rezero[i] = 0; }
        int chunk_total = warp_sums[31];
        __syncthreads();
        if (tid == 0) s_carry += chunk_total;
        __syncthreads();
    }
    if (tid == 0) rowptr[n] = s_carry;
}

__global__ void scan4(int* __restrict__ cnt,
                      int* rp0, int* rp1, int* rp2, int* rp3) {
    int t = blockIdx.x;
    int* rp = (t == 0) ? rp0 : (t == 1) ? rp1 : (t == 2) ? rp2 : rp3;
    int n = (t == 0) ? NTC : (t == 1) ? NPC : (t == 2) ? NFC : NPC;
    scan_body(cnt + t * NTC, rp, cnt + t * NTC, n);
}

__global__ void scatter4(const int* __restrict__ s0, const int* __restrict__ d0,
                         const int* __restrict__ s1, const int* __restrict__ d1,
                         const int* __restrict__ s2, const int* __restrict__ d2,
                         const int* __restrict__ s3, const int* __restrict__ d3,
                         const int* rp0, const int* rp1, const int* rp2, const int* rp3,
                         int* __restrict__ cnt,
                         int* c0, int* c1, int* c2, int* c3) {
    int t = blockIdx.y;
    const int* src = (t == 0) ? s0 : (t == 1) ? s1 : (t == 2) ? s2 : s3;
    const int* dst = (t == 0) ? d0 : (t == 1) ? d1 : (t == 2) ? d2 : d3;
    const int* rp  = (t == 0) ? rp0 : (t == 1) ? rp1 : (t == 2) ? rp2 : rp3;
    int* csr = (t == 0) ? c0 : (t == 1) ? c1 : (t == 2) ? c2 : c3;
    int* cur = cnt + t * NTC;
    int i = blockIdx.x * blockDim.x + threadIdx.x;
    if (i >= EC) return;
    int d = dst[i];
    int pos = rp[d] + atomicAdd(&cur[d], 1);
    csr[pos] = src[i];
}

// ---------------- score vectors for ALL layers ----------------
__global__ void vec_all(const float* __restrict__ Ws, const float* __restrict__ as,
                        const float* __restrict__ Wd, const float* __restrict__ ad,
                        float* __restrict__ wsv, float* __restrict__ wdv) {
    int idx = blockIdx.x * blockDim.x + threadIdx.x;
    if (idx >= 2 * 5 * 4 * 64) return;
    int which = idx >= 1280;
    int r = which ? idx - 1280 : idx;
    int i = r & 63, lt = r >> 6;
    const float* W = which ? Wd : Ws;
    const float* a = which ? ad : as;
    float* o = which ? wdv : wsv;
    float acc = 0.f;
    const float* wr = W + (size_t)(lt * 64 + i) * 64;
    const float* ar = a + lt * 64;
    #pragma unroll 8
    for (int j = 0; j < 64; j++) acc = fmaf(wr[j], ar[j], acc);
    o[r] = acc;
}

// ---------------- embed ----------------
__global__ void embed_k(const float* __restrict__ mass, const int* __restrict__ pstate,
                        const float* __restrict__ embW, const float* __restrict__ embS,
                        float* __restrict__ xp) {
    int idx = blockIdx.x * blockDim.x + threadIdx.x;
    if (idx >= NPC * 64) return;
    int n = idx >> 6, j = idx & 63;
    float v;
    if (j < 32) v = mass[n] * embW[j];
    else {
        int st = pstate[2 * n] + 2 * pstate[2 * n + 1];
        v = embS[st * 32 + (j - 32)];
    }
    xp[idx] = v;
}

// ---------------- up to 4 per-row dot products (layer-0 init) ----------------
__global__ void dot4(const float* __restrict__ X, int n,
                     const float* v0, float* o0, const float* v1, float* o1,
                     const float* v2, float* o2, const float* v3, float* o3) {
    int idx = blockIdx.x * blockDim.x + threadIdx.x;
    int w = idx >> 5;
    if (w >= n) return;
    int lane = idx & 31;
    float2 x = *(const float2*)&X[(size_t)w * 64 + lane * 2];
#define DODOT(v, o) if (v) { \
        float s = x.x * v[2 * lane] + x.y * v[2 * lane + 1]; \
        for (int off = 16; off; off >>= 1) s += __shfl_xor_sync(FULLMASK, s, off); \
        if (lane == 0) o[w] = s; }
    DODOT(v0, o0)
    DODOT(v1, o1)
    DODOT(v2, o2)
    DODOT(v3, o3)
#undef DODOT
}

// ---------------- warp-level online-softmax GAT row -> smem ----------------
__device__ __forceinline__ void gat_row(int d, int lane,
                                        const int* __restrict__ rp, const int* __restrict__ cs,
                                        const float* __restrict__ ss, const float* __restrict__ sd,
                                        const float* __restrict__ X, float* zrow) {
    int beg = rp[d], end = rp[d + 1];
    float m = -1e30f, s = 0.f, ax = 0.f, ay = 0.f;
    float sdv = sd[d];
    for (int base = beg; base < end; base += 32) {
        int j = base + lane;
        bool valid = (j < end);
        int src = valid ? cs[j] : 0;
        float e = -1e30f;
        if (valid) {
            float t = ss[src] + sdv;
            e = t > 0.f ? t : 0.2f * t;
        }
        float cm = e;
        #pragma unroll
        for (int o = 16; o; o >>= 1) cm = fmaxf(cm, __shfl_xor_sync(FULLMASK, cm, o));
        float nm = fmaxf(m, cm);
        float sc = expf(m - nm);           // first chunk: exp(-inf)=0, state already 0
        s *= sc; ax *= sc; ay *= sc;
        m = nm;
        float ex = valid ? expf(e - nm) : 0.f;
        float se = ex;
        #pragma unroll
        for (int o = 16; o; o >>= 1) se += __shfl_xor_sync(FULLMASK, se, o);
        s += se;
        int cnt = end - base; if (cnt > 32) cnt = 32;
        for (int k = 0; k < cnt; k++) {
            float wt = __shfl_sync(FULLMASK, ex, k);
            int sj = __shfl_sync(FULLMASK, src, k);
            float2 h = *(const float2*)&X[(size_t)sj * 64 + lane * 2];
            ax = fmaf(wt, h.x, ax);
            ay = fmaf(wt, h.y, ay);
        }
    }
    float inv = s > 0.f ? 1.f / s : 0.f;
    ((float2*)zrow)[lane] = make_float2(ax * inv, ay * inv);
}

// ---------------- fused GAT layer: softmax+gather -> smem -> transform + epilogue ----------------
__global__ void gat_layer(const int* rp1, const int* cs1, const float* ss1, const float* sd1,
                          const float* X1, const float* W1, const float* b1,
                          const int* rp2, const int* cs2, const float* ss2, const float* sd2,
                          const float* X2, const float* W2, const float* b2,
                          float* __restrict__ Y, int relu,
                          const float* v0, float* o0, const float* v1, float* o1,
                          const float* v2, float* o2, const float* v3, float* o3) {
    __shared__ float Zs[64 * 66];
    __shared__ float Wsh[64][68];
    int row0 = blockIdx.x * 64;
    int tid = threadIdx.x;              // 256
    int lane = tid & 31, w = tid >> 5;
    int tx = tid & 15, ty = tid >> 4;
    int c0 = tx * 4, r0 = ty * 4;
    float acc[4][4] = {};
    for (int p = 0; p < 2; p++) {
        const int* rp = p ? rp2 : rp1;
        if (!rp) break;
        const int* cs = p ? cs2 : cs1;
        const float* ss = p ? ss2 : ss1;
        const float* sd = p ? sd2 : sd1;
        const float* X = p ? X2 : X1;
        const float* W = p ? W2 : W1;
        const float4* W4 = (const float4*)W;
        for (int i = tid; i < 1024; i += 256) {
            float4 v = W4[i];
            int r = i >> 4, c = (i & 15) * 4;
            Wsh[r][c] = v.x; Wsh[r][c + 1] = v.y; Wsh[r][c + 2] = v.z; Wsh[r][c + 3] = v.w;
        }
        // phase 1: aggregate 8 rows per warp into Zs
        #pragma unroll 1
        for (int i = 0; i < 8; i++) {
            int r = w * 8 + i;
            gat_row(row0 + r, lane, rp, cs, ss, sd, X, &Zs[r * 66]);
        }
        __syncthreads();
        // phase 2: acc += Zs @ W
        #pragma unroll
        for (int k = 0; k < 64; k++) {
            float4 wv = *(const float4*)&Wsh[k][c0];
            float x0 = Zs[(r0) * 66 + k], x1 = Zs[(r0 + 1) * 66 + k];
            float x2 = Zs[(r0 + 2) * 66 + k], x3 = Zs[(r0 + 3) * 66 + k];
            acc[0][0] = fmaf(x0, wv.x, acc[0][0]); acc[0][1] = fmaf(x0, wv.y, acc[0][1]);
            acc[0][2] = fmaf(x0, wv.z, acc[0][2]); acc[0][3] = fmaf(x0, wv.w, acc[0][3]);
            acc[1][0] = fmaf(x1, wv.x, acc[1][0]); acc[1][1] = fmaf(x1, wv.y, acc[1][1]);
            acc[1][2] = fmaf(x1, wv.z, acc[1][2]); acc[1][3] = fmaf(x1, wv.w, acc[1][3]);
            acc[2][0] = fmaf(x2, wv.x, acc[2][0]); acc[2][1] = fmaf(x2, wv.y, acc[2][1]);
            acc[2][2] = fmaf(x2, wv.z, acc[2][2]); acc[2][3] = fmaf(x2, wv.w, acc[2][3]);
            acc[3][0] = fmaf(x3, wv.x, acc[3][0]); acc[3][1] = fmaf(x3, wv.y, acc[3][1]);
            acc[3][2] = fmaf(x3, wv.z, acc[3][2]); acc[3][3] = fmaf(x3, wv.w, acc[3][3]);
        }
        __syncthreads();
    }
    // bias + relu + store
    float bv[4];
    #pragma unroll
    for (int c = 0; c < 4; c++) bv[c] = b1[c0 + c] + (b2 ? b2[c0 + c] : 0.f);
    #pragma unroll
    for (int i = 0; i < 4; i++)
        #pragma unroll
        for (int c = 0; c < 4; c++) {
            float v = acc[i][c] + bv[c];
            if (relu) v = fmaxf(v, 0.f);
            acc[i][c] = v;
        }
    #pragma unroll
    for (int i = 0; i < 4; i++) {
        float4 o = make_float4(acc[i][0], acc[i][1], acc[i][2], acc[i][3]);
        *(float4*)&Y[((size_t)(row0 + r0 + i)) * 64 + c0] = o;
    }
    // epilogue dots for next layer's attention scores (into the OTHER score buffer)
#define DOVEC(v, o) if (v) { \
        float vv0 = v[c0], vv1 = v[c0 + 1], vv2 = v[c0 + 2], vv3 = v[c0 + 3]; \
        _Pragma("unroll") \
        for (int i = 0; i < 4; i++) { \
            float part = acc[i][0] * vv0 + acc[i][1] * vv1 + acc[i][2] * vv2 + acc[i][3] * vv3; \
            for (int off = 8; off; off >>= 1) part += __shfl_xor_sync(FULLMASK, part, off); \
            if (tx == 0) o[row0 + r0 + i] = part; \
        } }
    DOVEC(v0, o0)
    DOVEC(v1, o1)
    DOVEC(v2, o2)
    DOVEC(v3, o3)
#undef DOVEC
}

// ---------------- pooling ----------------
__global__ void pool_k(const float* __restrict__ x, int npg, float* __restrict__ rep, int off) {
    int b = blockIdx.x;
    int t = threadIdx.x;            // 256
    int d = t & 63, c = t >> 6;
    const float* base = x + (size_t)b * npg * 64;
    float mx = -1e30f, mn = 1e30f, sm = 0.f;
    for (int n = c; n < npg; n += 4) {
        float v = base[(size_t)n * 64 + d];
        mx = fmaxf(mx, v); mn = fminf(mn, v); sm += v;
    }
    __shared__ float smx[4][64], smn[4][64], ssm[4][64];
    smx[c][d] = mx; smn[c][d] = mn; ssm[c][d] = sm;
    __syncthreads();
    if (c == 0) {
        for (int i = 1; i < 4; i++) {
            mx = fmaxf(mx, smx[i][d]); mn = fminf(mn, smn[i][d]); sm += ssm[i][d];
        }
        rep[b * 576 + off + d] = mx;
        rep[b * 576 + off + 64 + d] = mn;
        rep[b * 576 + off + 128 + d] = sm / (float)npg;
    }
}

// ---------------- LayerNorm + out_a projection ----------------
__global__ void ln_ra(const float* __restrict__ ap, const float* __restrict__ g,
                      const float* __restrict__ be, const float* __restrict__ Wa,
                      const float* __restrict__ ba, float* __restrict__ ra) {
    int idx = blockIdx.x * blockDim.x + threadIdx.x;
    int n = idx >> 5;
    if (n >= NPC) return;
    int lane = idx & 31;
    float2 v = *(const float2*)&ap[(size_t)n * 64 + lane * 2];
    float sum = v.x + v.y;
    for (int o = 16; o; o >>= 1) sum += __shfl_xor_sync(FULLMASK, sum, o);
    float mu = sum * (1.f / 64.f);
    float dx = v.x - mu, dy = v.y - mu;
    float vs = dx * dx + dy * dy;
    for (int o = 16; o; o >>= 1) vs += __shfl_xor_sync(FULLMASK, vs, o);
    float rs = rsqrtf(vs * (1.f / 64.f) + 1e-5f);
    float y0 = dx * rs * g[2 * lane] + be[2 * lane];
    float y1 = dy * rs * g[2 * lane + 1] + be[2 * lane + 1];
    float r0 = y0 * Wa[(2 * lane) * 2]     + y1 * Wa[(2 * lane + 1) * 2];
    float r1 = y0 * Wa[(2 * lane) * 2 + 1] + y1 * Wa[(2 * lane + 1) * 2 + 1];
    for (int o = 16; o; o >>= 1) r0 += __shfl_xor_sync(FULLMASK, r0, o);
    for (int o = 16; o; o >>= 1) r1 += __shfl_xor_sync(FULLMASK, r1, o);
    if (lane == 0) {
        ra[2 * n]     = r0 + ba[0];
        ra[2 * n + 1] = r1 + ba[1];
    }
}

// ---------------- per-graph softmax + scatter to actions ----------------
__device__ __forceinline__ float blk64_max(float v, volatile float* sh) {
    for (int o = 16; o; o >>= 1) v = fmaxf(v, __shfl_xor_sync(FULLMASK, v, o));
    if ((threadIdx.x & 31) == 0) sh[threadIdx.x >> 5] = v;
    __syncthreads();
    float r = fmaxf(sh[0], sh[1]);
    __syncthreads();
    return r;
}
__device__ __forceinline__ float blk64_sum(float v, volatile float* sh) {
    for (int o = 16; o; o >>= 1) v += __shfl_xor_sync(FULLMASK, v, o);
    if ((threadIdx.x & 31) == 0) sh[threadIdx.x >> 5] = v;
    __syncthreads();
    float r = sh[0] + sh[1];
    __syncthreads();
    return r;
}

__global__ void act_softmax(const float* __restrict__ ra, const int* __restrict__ part_id,
                            float* __restrict__ out) {
    __shared__ float sh[2];
    int b = blockIdx.x, t = threadIdx.x;        // 64
    int n = b * 64 + t;
    float v0 = ra[2 * n], v1 = ra[2 * n + 1];
    float m0 = blk64_max(v0, sh);
    float m1 = blk64_max(v1, sh);
    float e0 = expf(v0 - m0), e1 = expf(v1 - m1);
    float s0 = blk64_sum(e0, sh);
    float s1 = blk64_sum(e1, sh);
    int p = part_id[n];
    out[b * 128 + p] = e0 / s0;
    out[b * 128 + 64 + p] = e1 / s1;
}

// ---------------- value head MLPs ----------------
__global__ void mlp_k(const float* __restrict__ in, int K, const float* __restrict__ W,
                      const float* __restrict__ bias, float* __restrict__ out) {
    __shared__ float s[576];
    int b = blockIdx.x, j = threadIdx.x;        // 64
    for (int k = j; k < K; k += 64) s[k] = in[b * K + k];
    __syncthreads();
    float acc = bias[j];
    for (int k = 0; k < K; k++) acc = fmaf(s[k], W[k * 64 + j], acc);
    acc = 0.5f * acc * (1.f + erff(acc * 0.70710678118654752f));
    out[b * 64 + j] = acc;
}

__global__ void mlp_out(const float* __restrict__ h, const float* __restrict__ Wo,
                        const float* __restrict__ bo, float* __restrict__ V) {
    int idx = blockIdx.x * blockDim.x + threadIdx.x;
    int b = idx >> 5;
    if (b >= BC) return;
    int lane = idx & 31;
    float2 v = *(const float2*)&h[b * 64 + lane * 2];
    float s = v.x * Wo[2 * lane] + v.y * Wo[2 * lane + 1];
    for (int o = 16; o; o >>= 1) s += __shfl_xor_sync(FULLMASK, s, o);
    if (lane == 0) V[b] = tanhf(s + bo[0]);
}

// ---------------- host ----------------
#define SYMF(p, s) do { void* _q; cudaGetSymbolAddress(&_q, s); p = (float*)_q; } while (0)
#define SYMI(p, s) do { void* _q; cudaGetSymbolAddress(&_q, s); p = (int*)_q; } while (0)

extern "C" void kernel_launch(void* const* d_in, const int* in_sizes, int n_in,
                              void* d_out, int out_size) {
    const float* mass      = (const float*)d_in[0];
    const int*   pstate    = (const int*)d_in[1];
    const float* torque_x  = (const float*)d_in[2];
    const float* force_x   = (const float*)d_in[3];
    const int* e_pt_src = (const int*)d_in[4];
    const int* e_pt_dst = (const int*)d_in[5];
    const int* e_tp_src = (const int*)d_in[6];
    const int* e_tp_dst = (const int*)d_in[7];
    const int* e_pf_src = (const int*)d_in[8];
    const int* e_pf_dst = (const int*)d_in[9];
    const int* e_fp_src = (const int*)d_in[10];
    const int* e_fp_dst = (const int*)d_in[11];
    const int* part_id  = (const int*)d_in[13];
    const float* embW   = (const float*)d_in[14];
    const float* embS   = (const float*)d_in[15];
    const float* W_src  = (const float*)d_in[16];
    const float* W_dst  = (const float*)d_in[17];
    const float* a_src  = (const float*)d_in[18];
    const float* a_dst  = (const float*)d_in[19];
    const float* b_conv = (const float*)d_in[20];
    const float* ln_g   = (const float*)d_in[21];
    const float* ln_b   = (const float*)d_in[22];
    const float* outaW  = (const float*)d_in[23];
    const float* outab  = (const float*)d_in[24];
    const float* innW   = (const float*)d_in[25];
    const float* innb   = (const float*)d_in[26];
    const float* fulW   = (const float*)d_in[27];
    const float* fulb   = (const float*)d_in[28];
    const float* outW   = (const float*)d_in[29];
    const float* outb   = (const float*)d_in[30];
    float* out = (float*)d_out;

    float *xp, *xt, *xf, *ap;
    float *ss_pt, *ss_pf, *sd_tp, *sd_fp, *ss_tp, *sd_pt, *ss_fp, *sd_pf;
    float *wsv, *wdv, *ra, *rep, *h1, *h2;
    int *rp_pt, *rp_pf, *rp_tp, *rp_fp, *cs_pt, *cs_tp, *cs_pf, *cs_fp, *cnt;
    SYMF(xp, g_xp); SYMF(xt, g_xt); SYMF(xf, g_xf); SYMF(ap, g_ap);
    SYMF(ss_pt, g_ss_pt); SYMF(ss_pf, g_ss_pf); SYMF(sd_tp, g_sd_tp); SYMF(sd_fp, g_sd_fp);
    SYMF(ss_tp, g_ss_tp); SYMF(sd_pt, g_sd_pt); SYMF(ss_fp, g_ss_fp); SYMF(sd_pf, g_sd_pf);
    SYMF(wsv, g_wsv); SYMF(wdv, g_wdv); SYMF(ra, g_ra);
    SYMF(rep, g_rep); SYMF(h1, g_h1); SYMF(h2, g_h2);
    SYMI(rp_pt, g_rp_pt); SYMI(rp_pf, g_rp_pf); SYMI(rp_tp, g_rp_tp); SYMI(rp_fp, g_rp_fp);
    SYMI(cs_pt, g_cs_pt); SYMI(cs_tp, g_cs_tp); SYMI(cs_pf, g_cs_pf); SYMI(cs_fp, g_cs_fp);
    SYMI(cnt, g_cnt);

    // batched CSR build: types 0=pt(dst t) 1=tp(dst p) 2=pf(dst f) 3=fp(dst p)
    zero4<<<(4 * NTC) / 256, 256>>>(cnt);
    { dim3 g(EC / 256, 4); hist4<<<g, 256>>>(e_pt_dst, e_tp_dst, e_pf_dst, e_fp_dst, cnt); }
    scan4<<<4, 1024>>>(cnt, rp_pt, rp_tp, rp_pf, rp_fp);
    { dim3 g(EC / 256, 4);
      scatter4<<<g, 256>>>(e_pt_src, e_pt_dst, e_tp_src, e_tp_dst,
                           e_pf_src, e_pf_dst, e_fp_src, e_fp_dst,
                           rp_pt, rp_tp, rp_pf, rp_fp, cnt,
                           cs_pt, cs_tp, cs_pf, cs_fp); }

    // score vectors; embed; layer-0 score dots (buffer 0)
    vec_all<<<10, 256>>>(W_src, a_src, W_dst, a_dst, wsv, wdv);
    dot4<<<(NTC * 32) / 256, 256>>>(torque_x, NTC,
         wsv + 1 * 64, ss_tp, wdv + 0 * 64, sd_pt, nullptr, nullptr, nullptr, nullptr);
    dot4<<<(NFC * 32) / 256, 256>>>(force_x, NFC,
         wsv + 3 * 64, ss_fp, wdv + 2 * 64, sd_pf, nullptr, nullptr, nullptr, nullptr);
    embed_k<<<(NPC * 64) / 256, 256>>>(mass, pstate, embW, embS, xp);
    dot4<<<(NPC * 32) / 256, 256>>>(xp, NPC,
         wsv + 0 * 64, ss_pt, wsv + 2 * 64, ss_pf,
         wdv + 1 * 64, sd_tp, wdv + 3 * 64, sd_fp);

    for (int l = 0; l < 5; l++) {
        const float* xpi = xp;
        // xt/xf ping-pong: layer l reads parity (l+1)&1, writes parity l&1
        const float* xti = (l == 0) ? torque_x : xt + (size_t)((l + 1) & 1) * NTC * 64;
        const float* xfi = (l == 0) ? force_x  : xf + (size_t)((l + 1) & 1) * NFC * 64;
        float* xto = xt + (size_t)(l & 1) * NTC * 64;
        float* xfo = xf + (size_t)(l & 1) * NFC * 64;
        const float* Wl = W_src + (size_t)l * 4 * 4096;
        const float* bl = b_conv + (size_t)l * 4 * 64;
        int relu = (l < 3) ? 1 : 0;
        int actor = (l == 4);
        const float* nwsv = wsv + (size_t)(l + 1) * 4 * 64;
        const float* nwdv = wdv + (size_t)(l + 1) * 4 * 64;
        // score buffers: read from parity l, write next into parity l+1
        int ci = l & 1, ni = (l + 1) & 1;
        const float* c_ss_pt = ss_pt + ci * NPC;  float* n_ss_pt = ss_pt + ni * NPC;
        const float* c_ss_pf = ss_pf + ci * NPC;  float* n_ss_pf = ss_pf + ni * NPC;
        const float* c_sd_tp = sd_tp + ci * NPC;  float* n_sd_tp = sd_tp + ni * NPC;
        const float* c_sd_fp = sd_fp + ci * NPC;  float* n_sd_fp = sd_fp + ni * NPC;
        const float* c_ss_tp = ss_tp + ci * NTC;  float* n_ss_tp = ss_tp + ni * NTC;
        const float* c_sd_pt = sd_pt + ci * NTC;  float* n_sd_pt = sd_pt + ni * NTC;
        const float* c_ss_fp = ss_fp + ci * NFC;  float* n_ss_fp = ss_fp + ni * NFC;
        const float* c_sd_pf = sd_pf + ci * NFC;  float* n_sd_pf = sd_pf + ni * NFC;

        if (!actor) {
            // dst = torque: edge type pt (src = p)
            gat_layer<<<NTC / 64, 256>>>(rp_pt, cs_pt, c_ss_pt, c_sd_pt, xpi,
                Wl + 0 * 4096, bl + 0 * 64,
                nullptr, nullptr, nullptr, nullptr, nullptr, nullptr, nullptr,
                xto, relu,
                nwsv + 1 * 64, n_ss_tp, nwdv + 0 * 64, n_sd_pt,
                nullptr, nullptr, nullptr, nullptr);
            // dst = force: edge type pf (src = p)
            gat_layer<<<NFC / 64, 256>>>(rp_pf, cs_pf, c_ss_pf, c_sd_pf, xpi,
                Wl + 2 * 4096, bl + 2 * 64,
                nullptr, nullptr, nullptr, nullptr, nullptr, nullptr, nullptr,
                xfo, relu,
                nwsv + 3 * 64, n_ss_fp, nwdv + 2 * 64, n_sd_pf,
                nullptr, nullptr, nullptr, nullptr);
            // dst = part: edge types tp (src = t, OLD buffer) + fp (src = f, OLD buffer)
            gat_layer<<<NPC / 64, 256>>>(rp_tp, cs_tp, c_ss_tp, c_sd_tp, xti,
                Wl + 1 * 4096, bl + 1 * 64,
                rp_fp, cs_fp, c_ss_fp, c_sd_fp, xfi, Wl + 3 * 4096, bl + 3 * 64,
                xp, relu,
                nwsv + 0 * 64, n_ss_pt, nwsv + 2 * 64, n_ss_pf,
                nwdv + 1 * 64, n_sd_tp, nwdv + 3 * 64, n_sd_fp);
        } else {
            gat_layer<<<NPC / 64, 256>>>(rp_tp, cs_tp, c_ss_tp, c_sd_tp, xti,
                Wl + 1 * 4096, bl + 1 * 64,
                rp_fp, cs_fp, c_ss_fp, c_sd_fp, xfi, Wl + 3 * 4096, bl + 3 * 64,
                ap, 0,
                nullptr, nullptr, nullptr, nullptr,
                nullptr, nullptr, nullptr, nullptr);
        }
    }

    // pooling over final x: layer 3 wrote xt/xf parity 1; xp in place
    pool_k<<<BC, 256>>>(xp, 64, rep, 0);
    pool_k<<<BC, 256>>>(xt + (size_t)NTC * 64, 512, rep, 192);
    pool_k<<<BC, 256>>>(xf + (size_t)NFC * 64, 512, rep, 384);

    // actor head
    ln_ra<<<(NPC * 32) / 256, 256>>>(ap, ln_g, ln_b, outaW, outab, ra);
    act_softmax<<<BC, 64>>>(ra, part_id, out);

    // value head
    mlp_k<<<BC, 64>>>(rep, 576, innW, innb, h1);
    mlp_k<<<BC, 64>>>(h1, 64, fulW, fulb, h2);
    mlp_out<<<(BC * 32) / 256, 256>>>(h2, outW, outb, out + BC * 128);
}

// round 7
// speedup vs baseline: 1.1800x; 1.1800x over previous
#include <cuda_runtime.h>
#include <math.h>

#define NPC 16384
#define NTC 131072
#define NFC 131072
#define EC  262144
#define BC  256
#define FULLMASK 0xffffffffu

// ---------------- device scratch ----------------
__device__ float g_xp[NPC * 64];
__device__ float g_xt[2][NTC * 64];     // ping-pong
__device__ float g_xf[2][NFC * 64];
__device__ float g_ap[NPC * 64];
__device__ float g_ss_pt[2][NPC], g_ss_pf[2][NPC], g_sd_tp[2][NPC], g_sd_fp[2][NPC];
__device__ float g_ss_tp[2][NTC], g_sd_pt[2][NTC];
__device__ float g_ss_fp[2][NFC], g_sd_pf[2][NFC];
__device__ float g_wsv[5 * 4 * 64], g_wdv[5 * 4 * 64];
__device__ int g_rp_pt[NTC + 1], g_rp_pf[NFC + 1];
__device__ int g_rp_tp[NPC + 1], g_rp_fp[NPC + 1];
__device__ int g_cs_pt[EC], g_cs_tp[EC], g_cs_pf[EC], g_cs_fp[EC];
__device__ int g_cnt[4 * NTC];
__device__ float g_ra[NPC * 2];
__device__ float g_rep[BC * 576];
__device__ float g_h1[BC * 64], g_h2[BC * 64];

// ---------------- batched CSR build ----------------
__global__ void zero4(int* c) {
    int i = blockIdx.x * blockDim.x + threadIdx.x;
    if (i < 4 * NTC) c[i] = 0;
}

__global__ void hist4(const int* __restrict__ d0, const int* __restrict__ d1,
                      const int* __restrict__ d2, const int* __restrict__ d3,
                      int* __restrict__ cnt) {
    int t = blockIdx.y;
    const int* d = (t == 0) ? d0 : (t == 1) ? d1 : (t == 2) ? d2 : d3;
    int* c = cnt + t * NTC;
    int i = blockIdx.x * blockDim.x + threadIdx.x;
    if (i < EC) atomicAdd(&c[d[i]], 1);
}

__device__ void scan_body(const int* __restrict__ deg, int* __restrict__ rowptr,
                          int* __restrict__ rezero, int n) {
    __shared__ int warp_sums[32];
    __shared__ int s_carry;
    int tid = threadIdx.x;
    int lane = tid & 31, wid = tid >> 5;
    if (tid == 0) s_carry = 0;
    __syncthreads();
    for (int base = 0; base < n; base += 1024) {
        int i = base + tid;
        int v = (i < n) ? deg[i] : 0;
        int x = v;
        #pragma unroll
        for (int off = 1; off < 32; off <<= 1) {
            int y = __shfl_up_sync(FULLMASK, x, off);
            if (lane >= off) x += y;
        }
        if (lane == 31) warp_sums[wid] = x;
        __syncthreads();
        if (tid < 32) {
            int s = warp_sums[tid];
            #pragma unroll
            for (int off = 1; off < 32; off <<= 1) {
                int y = __shfl_up_sync(FULLMASK, s, off);
                if (tid >= off) s += y;
            }
            warp_sums[tid] = s;
        }
        __syncthreads();
        int incl = x + (wid ? warp_sums[wid - 1] : 0);
        if (i < n) { rowptr[i] = s_carry + incl - v; rezero[i] = 0; }
        int chunk_total = warp_sums[31];
        __syncthreads();
        if (tid == 0) s_carry += chunk_total;
        __syncthreads();
    }
    if (tid == 0) rowptr[n] = s_carry;
}

__global__ void scan4(int* __restrict__ cnt,
                      int* rp0, int* rp1, int* rp2, int* rp3) {
    int t = blockIdx.x;
    int* rp = (t == 0) ? rp0 : (t == 1) ? rp1 : (t == 2) ? rp2 : rp3;
    int n = (t == 0) ? NTC : (t == 1) ? NPC : (t == 2) ? NFC : NPC;
    scan_body(cnt + t * NTC, rp, cnt + t * NTC, n);
}

__global__ void scatter4(const int* __restrict__ s0, const int* __restrict__ d0,
                         const int* __restrict__ s1, const int* __restrict__ d1,
                         const int* __restrict__ s2, const int* __restrict__ d2,
                         const int* __restrict__ s3, const int* __restrict__ d3,
                         const int* rp0, const int* rp1, const int* rp2, const int* rp3,
                         int* __restrict__ cnt,
                         int* c0, int* c1, int* c2, int* c3) {
    int t = blockIdx.y;
    const int* src = (t == 0) ? s0 : (t == 1) ? s1 : (t == 2) ? s2 : s3;
    const int* dst = (t == 0) ? d0 : (t == 1) ? d1 : (t == 2) ? d2 : d3;
    const int* rp  = (t == 0) ? rp0 : (t == 1) ? rp1 : (t == 2) ? rp2 : rp3;
    int* csr = (t == 0) ? c0 : (t == 1) ? c1 : (t == 2) ? c2 : c3;
    int* cur = cnt + t * NTC;
    int i = blockIdx.x * blockDim.x + threadIdx.x;
    if (i >= EC) return;
    int d = dst[i];
    int pos = rp[d] + atomicAdd(&cur[d], 1);
    csr[pos] = src[i];
}

// ---------------- score vectors for ALL layers ----------------
__global__ void vec_all(const float* __restrict__ Ws, const float* __restrict__ as,
                        const float* __restrict__ Wd, const float* __restrict__ ad,
                        float* __restrict__ wsv, float* __restrict__ wdv) {
    int idx = blockIdx.x * blockDim.x + threadIdx.x;
    if (idx >= 2 * 5 * 4 * 64) return;
    int which = idx >= 1280;
    int r = which ? idx - 1280 : idx;
    int i = r & 63, lt = r >> 6;
    const float* W = which ? Wd : Ws;
    const float* a = which ? ad : as;
    float* o = which ? wdv : wsv;
    float acc = 0.f;
    const float* wr = W + (size_t)(lt * 64 + i) * 64;
    const float* ar = a + lt * 64;
    #pragma unroll 8
    for (int j = 0; j < 64; j++) acc = fmaf(wr[j], ar[j], acc);
    o[r] = acc;
}

// ---------------- embed ----------------
__global__ void embed_k(const float* __restrict__ mass, const int* __restrict__ pstate,
                        const float* __restrict__ embW, const float* __restrict__ embS,
                        float* __restrict__ xp) {
    int idx = blockIdx.x * blockDim.x + threadIdx.x;
    if (idx >= NPC * 64) return;
    int n = idx >> 6, j = idx & 63;
    float v;
    if (j < 32) v = mass[n] * embW[j];
    else {
        int st = pstate[2 * n] + 2 * pstate[2 * n + 1];
        v = embS[st * 32 + (j - 32)];
    }
    xp[idx] = v;
}

// ---------------- up to 4 per-row dot products (layer-0 init) ----------------
__global__ void dot4(const float* __restrict__ X, int n,
                     const float* v0, float* o0, const float* v1, float* o1,
                     const float* v2, float* o2, const float* v3, float* o3) {
    int idx = blockIdx.x * blockDim.x + threadIdx.x;
    int w = idx >> 5;
    if (w >= n) return;
    int lane = idx & 31;
    float2 x = *(const float2*)&X[(size_t)w * 64 + lane * 2];
#define DODOT(v, o) if (v) { \
        float s = x.x * v[2 * lane] + x.y * v[2 * lane + 1]; \
        for (int off = 16; off; off >>= 1) s += __shfl_xor_sync(FULLMASK, s, off); \
        if (lane == 0) o[w] = s; }
    DODOT(v0, o0)
    DODOT(v1, o1)
    DODOT(v2, o2)
    DODOT(v3, o3)
#undef DODOT
}

// ---------------- phase 1: half-warp (16-lane) online-softmax GAT rows -> smem ----------------
// Each warp processes RPB/16 rows as RPB/32 concurrent pairs (lanes 0-15 row A, 16-31 row B).
template<int RPB>
__device__ __forceinline__ void gat_phase1(int row0,
        const int* __restrict__ rp, const int* __restrict__ cs,
        const float* __restrict__ ss, const float* __restrict__ sd,
        const float* __restrict__ X, float* __restrict__ Zs) {
    int tid = threadIdx.x;
    int lane = tid & 31, w = tid >> 5;       // 16 warps
    int half = lane >> 4;
    int hl = lane & 15;
    unsigned hmask = half ? 0xFFFF0000u : 0x0000FFFFu;
    int gb = half << 4;
    const float4* X4 = (const float4*)X;
    #pragma unroll
    for (int p = 0; p < RPB / 32; p++) {
        int r = w * (RPB / 16) + p * 2 + half;
        int d = row0 + r;
        int beg = rp[d], end = rp[d + 1];
        float sdv = sd[d];
        float m = -1e30f, s = 0.f;
        float4 acc = make_float4(0.f, 0.f, 0.f, 0.f);
        for (int base = beg; base < end; base += 16) {
            int j = base + hl;
            bool valid = j < end;
            int src = valid ? cs[j] : 0;
            float e = -1e30f;
            if (valid) {
                float t = ss[src] + sdv;
                e = t > 0.f ? t : 0.2f * t;
            }
            float cm = e;
            #pragma unroll
            for (int o = 8; o; o >>= 1) cm = fmaxf(cm, __shfl_xor_sync(hmask, cm, o));
            float nm = fmaxf(m, cm);
            float sc = __expf(m - nm);       // first chunk: exp(-huge)=0, state already 0
            s *= sc; acc.x *= sc; acc.y *= sc; acc.z *= sc; acc.w *= sc;
            m = nm;
            float ex = valid ? __expf(e - nm) : 0.f;
            float se = ex;
            #pragma unroll
            for (int o = 8; o; o >>= 1) se += __shfl_xor_sync(hmask, se, o);
            s += se;
            int cnt = end - base; if (cnt > 16) cnt = 16;
            int k = 0;
            for (; k + 4 <= cnt; k += 4) {
                float w0 = __shfl_sync(hmask, ex, gb + k);
                float w1 = __shfl_sync(hmask, ex, gb + k + 1);
                float w2 = __shfl_sync(hmask, ex, gb + k + 2);
                float w3 = __shfl_sync(hmask, ex, gb + k + 3);
                int s0 = __shfl_sync(hmask, src, gb + k);
                int s1 = __shfl_sync(hmask, src, gb + k + 1);
                int s2 = __shfl_sync(hmask, src, gb + k + 2);
                int s3 = __shfl_sync(hmask, src, gb + k + 3);
                float4 h0 = X4[(size_t)s0 * 16 + hl];
                float4 h1 = X4[(size_t)s1 * 16 + hl];
                float4 h2 = X4[(size_t)s2 * 16 + hl];
                float4 h3 = X4[(size_t)s3 * 16 + hl];
                acc.x = fmaf(w0, h0.x, acc.x); acc.y = fmaf(w0, h0.y, acc.y);
                acc.z = fmaf(w0, h0.z, acc.z); acc.w = fmaf(w0, h0.w, acc.w);
                acc.x = fmaf(w1, h1.x, acc.x); acc.y = fmaf(w1, h1.y, acc.y);
                acc.z = fmaf(w1, h1.z, acc.z); acc.w = fmaf(w1, h1.w, acc.w);
                acc.x = fmaf(w2, h2.x, acc.x); acc.y = fmaf(w2, h2.y, acc.y);
                acc.z = fmaf(w2, h2.z, acc.z); acc.w = fmaf(w2, h2.w, acc.w);
                acc.x = fmaf(w3, h3.x, acc.x); acc.y = fmaf(w3, h3.y, acc.y);
                acc.z = fmaf(w3, h3.z, acc.z); acc.w = fmaf(w3, h3.w, acc.w);
            }
            for (; k < cnt; k++) {
                float wt = __shfl_sync(hmask, ex, gb + k);
                int sj = __shfl_sync(hmask, src, gb + k);
                float4 h = X4[(size_t)sj * 16 + hl];
                acc.x = fmaf(wt, h.x, acc.x); acc.y = fmaf(wt, h.y, acc.y);
                acc.z = fmaf(wt, h.z, acc.z); acc.w = fmaf(wt, h.w, acc.w);
            }
        }
        float inv = s > 0.f ? 1.f / s : 0.f;
        ((float4*)&Zs[r * 68])[hl] = make_float4(acc.x * inv, acc.y * inv, acc.z * inv, acc.w * inv);
    }
}

__device__ __forceinline__ void load_W(const float* __restrict__ W, float (*Wsh)[68]) {
    const float4* W4 = (const float4*)W;
    for (int i = threadIdx.x; i < 1024; i += 512) {
        float4 v = W4[i];
        int r = i >> 4, c = (i & 15) * 4;
        Wsh[r][c] = v.x; Wsh[r][c + 1] = v.y; Wsh[r][c + 2] = v.z; Wsh[r][c + 3] = v.w;
    }
}

// ---------------- merged t-dst + f-dst kernel (64 rows/block, 512 threads) ----------------
__global__ void __launch_bounds__(512) gat_tf(int nA,
        const int* rpA, const int* csA, const float* ssA, const float* sdA,
        const float* XA, const float* WA, const float* bA, float* YA,
        const float* vA0, float* oA0, const float* vA1, float* oA1,
        const int* rpB, const int* csB, const float* ssB, const float* sdB,
        const float* XB, const float* WB, const float* bB, float* YB,
        const float* vB0, float* oB0, const float* vB1, float* oB1,
        int relu) {
    __shared__ float Zs[64 * 68];
    __shared__ float Wsh[64][68];
    bool isA = (int)blockIdx.x < nA;
    int row0 = (isA ? blockIdx.x : blockIdx.x - nA) * 64;
    const int* rp = isA ? rpA : rpB;
    const int* cs = isA ? csA : csB;
    const float* ss = isA ? ssA : ssB;
    const float* sd = isA ? sdA : sdB;
    const float* X = isA ? XA : XB;
    const float* W = isA ? WA : WB;
    const float* b = isA ? bA : bB;
    float* Y = isA ? YA : YB;
    const float* v0 = isA ? vA0 : vB0;  float* o0 = isA ? oA0 : oB0;
    const float* v1 = isA ? vA1 : vB1;  float* o1 = isA ? oA1 : oB1;

    load_W(W, Wsh);
    gat_phase1<64>(row0, rp, cs, ss, sd, X, Zs);
    __syncthreads();

    int tid = threadIdx.x;
    int lane = tid & 31;
    int tx = tid & 15, ty = tid >> 4;       // ty 0..31
    int c0 = tx * 4, r0 = ty * 2;
    float acc[2][4] = {};
    #pragma unroll
    for (int k = 0; k < 64; k++) {
        float4 wv = *(const float4*)&Wsh[k][c0];
        float x0 = Zs[r0 * 68 + k], x1 = Zs[(r0 + 1) * 68 + k];
        acc[0][0] = fmaf(x0, wv.x, acc[0][0]); acc[0][1] = fmaf(x0, wv.y, acc[0][1]);
        acc[0][2] = fmaf(x0, wv.z, acc[0][2]); acc[0][3] = fmaf(x0, wv.w, acc[0][3]);
        acc[1][0] = fmaf(x1, wv.x, acc[1][0]); acc[1][1] = fmaf(x1, wv.y, acc[1][1]);
        acc[1][2] = fmaf(x1, wv.z, acc[1][2]); acc[1][3] = fmaf(x1, wv.w, acc[1][3]);
    }
    #pragma unroll
    for (int i = 0; i < 2; i++) {
        #pragma unroll
        for (int c = 0; c < 4; c++) {
            float v = acc[i][c] + b[c0 + c];
            if (relu) v = fmaxf(v, 0.f);
            acc[i][c] = v;
        }
        *(float4*)&Y[((size_t)(row0 + r0 + i)) * 64 + c0] =
            make_float4(acc[i][0], acc[i][1], acc[i][2], acc[i][3]);
    }
    unsigned hmask = (lane & 16) ? 0xFFFF0000u : 0x0000FFFFu;
#define DOVEC(v, o) { \
        float vv0 = v[c0], vv1 = v[c0 + 1], vv2 = v[c0 + 2], vv3 = v[c0 + 3]; \
        _Pragma("unroll") \
        for (int i = 0; i < 2; i++) { \
            float part = acc[i][0] * vv0 + acc[i][1] * vv1 + acc[i][2] * vv2 + acc[i][3] * vv3; \
            for (int off = 8; off; off >>= 1) part += __shfl_xor_sync(hmask, part, off); \
            if ((lane & 15) == 0) o[row0 + r0 + i] = part; \
        } }
    DOVEC(v0, o0)
    DOVEC(v1, o1)
#undef DOVEC
}

// ---------------- p-dst kernel: dual edge types (32 rows/block, 512 threads) ----------------
__global__ void __launch_bounds__(512) gat_p(
        const int* rp1, const int* cs1, const float* ss1, const float* sd1,
        const float* X1, const float* W1, const float* b1,
        const int* rp2, const int* cs2, const float* ss2, const float* sd2,
        const float* X2, const float* W2, const float* b2,
        float* __restrict__ Y, int relu,
        const float* v0, float* o0, const float* v1, float* o1,
        const float* v2, float* o2, const float* v3, float* o3) {
    __shared__ float Zs[32 * 68];
    __shared__ float Wsh[64][68];
    int row0 = blockIdx.x * 32;
    int tid = threadIdx.x;
    int lane = tid & 31;
    int tx = tid & 15, ty = tid >> 4;       // ty 0..31 = row
    int c0 = tx * 4;
    float acc[4] = {};

    // type 1
    load_W(W1, Wsh);
    gat_phase1<32>(row0, rp1, cs1, ss1, sd1, X1, Zs);
    __syncthreads();
    #pragma unroll
    for (int k = 0; k < 64; k++) {
        float4 wv = *(const float4*)&Wsh[k][c0];
        float x0 = Zs[ty * 68 + k];
        acc[0] = fmaf(x0, wv.x, acc[0]); acc[1] = fmaf(x0, wv.y, acc[1]);
        acc[2] = fmaf(x0, wv.z, acc[2]); acc[3] = fmaf(x0, wv.w, acc[3]);
    }
    __syncthreads();
    // type 2
    load_W(W2, Wsh);
    gat_phase1<32>(row0, rp2, cs2, ss2, sd2, X2, Zs);
    __syncthreads();
    #pragma unroll
    for (int k = 0; k < 64; k++) {
        float4 wv = *(const float4*)&Wsh[k][c0];
        float x0 = Zs[ty * 68 + k];
        acc[0] = fmaf(x0, wv.x, acc[0]); acc[1] = fmaf(x0, wv.y, acc[1]);
        acc[2] = fmaf(x0, wv.z, acc[2]); acc[3] = fmaf(x0, wv.w, acc[3]);
    }

    #pragma unroll
    for (int c = 0; c < 4; c++) {
        float v = acc[c] + b1[c0 + c] + b2[c0 + c];
        if (relu) v = fmaxf(v, 0.f);
        acc[c] = v;
    }
    *(float4*)&Y[((size_t)(row0 + ty)) * 64 + c0] = make_float4(acc[0], acc[1], acc[2], acc[3]);

    unsigned hmask = (lane & 16) ? 0xFFFF0000u : 0x0000FFFFu;
#define DOVEC(v, o) if (v) { \
        float part = acc[0] * v[c0] + acc[1] * v[c0 + 1] + acc[2] * v[c0 + 2] + acc[3] * v[c0 + 3]; \
        for (int off = 8; off; off >>= 1) part += __shfl_xor_sync(hmask, part, off); \
        if ((lane & 15) == 0) o[row0 + ty] = part; }
    DOVEC(v0, o0)
    DOVEC(v1, o1)
    DOVEC(v2, o2)
    DOVEC(v3, o3)
#undef DOVEC
}

// ---------------- pooling ----------------
__global__ void pool_k(const float* __restrict__ x, int npg, float* __restrict__ rep, int off) {
    int b = blockIdx.x;
    int t = threadIdx.x;            // 256
    int d = t & 63, c = t >> 6;
    const float* base = x + (size_t)b * npg * 64;
    float mx = -1e30f, mn = 1e30f, sm = 0.f;
    for (int n = c; n < npg; n += 4) {
        float v = base[(size_t)n * 64 + d];
        mx = fmaxf(mx, v); mn = fminf(mn, v); sm += v;
    }
    __shared__ float smx[4][64], smn[4][64], ssm[4][64];
    smx[c][d] = mx; smn[c][d] = mn; ssm[c][d] = sm;
    __syncthreads();
    if (c == 0) {
        for (int i = 1; i < 4; i++) {
            mx = fmaxf(mx, smx[i][d]); mn = fminf(mn, smn[i][d]); sm += ssm[i][d];
        }
        rep[b * 576 + off + d] = mx;
        rep[b * 576 + off + 64 + d] = mn;
        rep[b * 576 + off + 128 + d] = sm / (float)npg;
    }
}

// ---------------- LayerNorm + out_a projection ----------------
__global__ void ln_ra(const float* __restrict__ ap, const float* __restrict__ g,
                      const float* __restrict__ be, const float* __restrict__ Wa,
                      const float* __restrict__ ba, float* __restrict__ ra) {
    int idx = blockIdx.x * blockDim.x + threadIdx.x;
    int n = idx >> 5;
    if (n >= NPC) return;
    int lane = idx & 31;
    float2 v = *(const float2*)&ap[(size_t)n * 64 + lane * 2];
    float sum = v.x + v.y;
    for (int o = 16; o; o >>= 1) sum += __shfl_xor_sync(FULLMASK, sum, o);
    float mu = sum * (1.f / 64.f);
    float dx = v.x - mu, dy = v.y - mu;
    float vs = dx * dx + dy * dy;
    for (int o = 16; o; o >>= 1) vs += __shfl_xor_sync(FULLMASK, vs, o);
    float rs = rsqrtf(vs * (1.f / 64.f) + 1e-5f);
    float y0 = dx * rs * g[2 * lane] + be[2 * lane];
    float y1 = dy * rs * g[2 * lane + 1] + be[2 * lane + 1];
    float r0 = y0 * Wa[(2 * lane) * 2]     + y1 * Wa[(2 * lane + 1) * 2];
    float r1 = y0 * Wa[(2 * lane) * 2 + 1] + y1 * Wa[(2 * lane + 1) * 2 + 1];
    for (int o = 16; o; o >>= 1) r0 += __shfl_xor_sync(FULLMASK, r0, o);
    for (int o = 16; o; o >>= 1) r1 += __shfl_xor_sync(FULLMASK, r1, o);
    if (lane == 0) {
        ra[2 * n]     = r0 + ba[0];
        ra[2 * n + 1] = r1 + ba[1];
    }
}

// ---------------- per-graph softmax + scatter to actions ----------------
__device__ __forceinline__ float blk64_max(float v, volatile float* sh) {
    for (int o = 16; o; o >>= 1) v = fmaxf(v, __shfl_xor_sync(FULLMASK, v, o));
    if ((threadIdx.x & 31) == 0) sh[threadIdx.x >> 5] = v;
    __syncthreads();
    float r = fmaxf(sh[0], sh[1]);
    __syncthreads();
    return r;
}
__device__ __forceinline__ float blk64_sum(float v, volatile float* sh) {
    for (int o = 16; o; o >>= 1) v += __shfl_xor_sync(FULLMASK, v, o);
    if ((threadIdx.x & 31) == 0) sh[threadIdx.x >> 5] = v;
    __syncthreads();
    float r = sh[0] + sh[1];
    __syncthreads();
    return r;
}

__global__ void act_softmax(const float* __restrict__ ra, const int* __restrict__ part_id,
                            float* __restrict__ out) {
    __shared__ float sh[2];
    int b = blockIdx.x, t = threadIdx.x;        // 64
    int n = b * 64 + t;
    float v0 = ra[2 * n], v1 = ra[2 * n + 1];
    float m0 = blk64_max(v0, sh);
    float m1 = blk64_max(v1, sh);
    float e0 = expf(v0 - m0), e1 = expf(v1 - m1);
    float s0 = blk64_sum(e0, sh);
    float s1 = blk64_sum(e1, sh);
    int p = part_id[n];
    out[b * 128 + p] = e0 / s0;
    out[b * 128 + 64 + p] = e1 / s1;
}

// ---------------- value head MLPs ----------------
__global__ void mlp_k(const float* __restrict__ in, int K, const float* __restrict__ W,
                      const float* __restrict__ bias, float* __restrict__ out) {
    __shared__ float s[576];
    int b = blockIdx.x, j = threadIdx.x;        // 64
    for (int k = j; k < K; k += 64) s[k] = in[b * K + k];
    __syncthreads();
    float acc = bias[j];
    for (int k = 0; k < K; k++) acc = fmaf(s[k], W[k * 64 + j], acc);
    acc = 0.5f * acc * (1.f + erff(acc * 0.70710678118654752f));
    out[b * 64 + j] = acc;
}

__global__ void mlp_out(const float* __restrict__ h, const float* __restrict__ Wo,
                        const float* __restrict__ bo, float* __restrict__ V) {
    int idx = blockIdx.x * blockDim.x + threadIdx.x;
    int b = idx >> 5;
    if (b >= BC) return;
    int lane = idx & 31;
    float2 v = *(const float2*)&h[b * 64 + lane * 2];
    float s = v.x * Wo[2 * lane] + v.y * Wo[2 * lane + 1];
    for (int o = 16; o; o >>= 1) s += __shfl_xor_sync(FULLMASK, s, o);
    if (lane == 0) V[b] = tanhf(s + bo[0]);
}

// ---------------- host ----------------
#define SYMF(p, s) do { void* _q; cudaGetSymbolAddress(&_q, s); p = (float*)_q; } while (0)
#define SYMI(p, s) do { void* _q; cudaGetSymbolAddress(&_q, s); p = (int*)_q; } while (0)

extern "C" void kernel_launch(void* const* d_in, const int* in_sizes, int n_in,
                              void* d_out, int out_size) {
    const float* mass      = (const float*)d_in[0];
    const int*   pstate    = (const int*)d_in[1];
    const float* torque_x  = (const float*)d_in[2];
    const float* force_x   = (const float*)d_in[3];
    const int* e_pt_src = (const int*)d_in[4];
    const int* e_pt_dst = (const int*)d_in[5];
    const int* e_tp_src = (const int*)d_in[6];
    const int* e_tp_dst = (const int*)d_in[7];
    const int* e_pf_src = (const int*)d_in[8];
    const int* e_pf_dst = (const int*)d_in[9];
    const int* e_fp_src = (const int*)d_in[10];
    const int* e_fp_dst = (const int*)d_in[11];
    const int* part_id  = (const int*)d_in[13];
    const float* embW   = (const float*)d_in[14];
    const float* embS   = (const float*)d_in[15];
    const float* W_src  = (const float*)d_in[16];
    const float* W_dst  = (const float*)d_in[17];
    const float* a_src  = (const float*)d_in[18];
    const float* a_dst  = (const float*)d_in[19];
    const float* b_conv = (const float*)d_in[20];
    const float* ln_g   = (const float*)d_in[21];
    const float* ln_b   = (const float*)d_in[22];
    const float* outaW  = (const float*)d_in[23];
    const float* outab  = (const float*)d_in[24];
    const float* innW   = (const float*)d_in[25];
    const float* innb   = (const float*)d_in[26];
    const float* fulW   = (const float*)d_in[27];
    const float* fulb   = (const float*)d_in[28];
    const float* outW   = (const float*)d_in[29];
    const float* outb   = (const float*)d_in[30];
    float* out = (float*)d_out;

    float *xp, *xt, *xf, *ap;
    float *ss_pt, *ss_pf, *sd_tp, *sd_fp, *ss_tp, *sd_pt, *ss_fp, *sd_pf;
    float *wsv, *wdv, *ra, *rep, *h1, *h2;
    int *rp_pt, *rp_pf, *rp_tp, *rp_fp, *cs_pt, *cs_tp, *cs_pf, *cs_fp, *cnt;
    SYMF(xp, g_xp); SYMF(xt, g_xt); SYMF(xf, g_xf); SYMF(ap, g_ap);
    SYMF(ss_pt, g_ss_pt); SYMF(ss_pf, g_ss_pf); SYMF(sd_tp, g_sd_tp); SYMF(sd_fp, g_sd_fp);
    SYMF(ss_tp, g_ss_tp); SYMF(sd_pt, g_sd_pt); SYMF(ss_fp, g_ss_fp); SYMF(sd_pf, g_sd_pf);
    SYMF(wsv, g_wsv); SYMF(wdv, g_wdv); SYMF(ra, g_ra);
    SYMF(rep, g_rep); SYMF(h1, g_h1); SYMF(h2, g_h2);
    SYMI(rp_pt, g_rp_pt); SYMI(rp_pf, g_rp_pf); SYMI(rp_tp, g_rp_tp); SYMI(rp_fp, g_rp_fp);
    SYMI(cs_pt, g_cs_pt); SYMI(cs_tp, g_cs_tp); SYMI(cs_pf, g_cs_pf); SYMI(cs_fp, g_cs_fp);
    SYMI(cnt, g_cnt);

    // batched CSR build
    zero4<<<(4 * NTC) / 256, 256>>>(cnt);
    { dim3 g(EC / 256, 4); hist4<<<g, 256>>>(e_pt_dst, e_tp_dst, e_pf_dst, e_fp_dst, cnt); }
    scan4<<<4, 1024>>>(cnt, rp_pt, rp_tp, rp_pf, rp_fp);
    { dim3 g(EC / 256, 4);
      scatter4<<<g, 256>>>(e_pt_src, e_pt_dst, e_tp_src, e_tp_dst,
                           e_pf_src, e_pf_dst, e_fp_src, e_fp_dst,
                           rp_pt, rp_tp, rp_pf, rp_fp, cnt,
                           cs_pt, cs_tp, cs_pf, cs_fp); }

    // score vectors; embed; layer-0 score dots (buffer 0)
    vec_all<<<10, 256>>>(W_src, a_src, W_dst, a_dst, wsv, wdv);
    dot4<<<(NTC * 32) / 256, 256>>>(torque_x, NTC,
         wsv + 1 * 64, ss_tp, wdv + 0 * 64, sd_pt, nullptr, nullptr, nullptr, nullptr);
    dot4<<<(NFC * 32) / 256, 256>>>(force_x, NFC,
         wsv + 3 * 64, ss_fp, wdv + 2 * 64, sd_pf, nullptr, nullptr, nullptr, nullptr);
    embed_k<<<(NPC * 64) / 256, 256>>>(mass, pstate, embW, embS, xp);
    dot4<<<(NPC * 32) / 256, 256>>>(xp, NPC,
         wsv + 0 * 64, ss_pt, wsv + 2 * 64, ss_pf,
         wdv + 1 * 64, sd_tp, wdv + 3 * 64, sd_fp);

    for (int l = 0; l < 5; l++) {
        const float* xpi = xp;
        const float* xti = (l == 0) ? torque_x : xt + (size_t)((l + 1) & 1) * NTC * 64;
        const float* xfi = (l == 0) ? force_x  : xf + (size_t)((l + 1) & 1) * NFC * 64;
        float* xto = xt + (size_t)(l & 1) * NTC * 64;
        float* xfo = xf + (size_t)(l & 1) * NFC * 64;
        const float* Wl = W_src + (size_t)l * 4 * 4096;
        const float* bl = b_conv + (size_t)l * 4 * 64;
        int relu = (l < 3) ? 1 : 0;
        int actor = (l == 4);
        const float* nwsv = wsv + (size_t)(l + 1) * 4 * 64;
        const float* nwdv = wdv + (size_t)(l + 1) * 4 * 64;
        int ci = l & 1, ni = (l + 1) & 1;
        const float* c_ss_pt = ss_pt + ci * NPC;  float* n_ss_pt = ss_pt + ni * NPC;
        const float* c_ss_pf = ss_pf + ci * NPC;  float* n_ss_pf = ss_pf + ni * NPC;
        const float* c_sd_tp = sd_tp + ci * NPC;  float* n_sd_tp = sd_tp + ni * NPC;
        const float* c_sd_fp = sd_fp + ci * NPC;  float* n_sd_fp = sd_fp + ni * NPC;
        const float* c_ss_tp = ss_tp + ci * NTC;  float* n_ss_tp = ss_tp + ni * NTC;
        const float* c_sd_pt = sd_pt + ci * NTC;  float* n_sd_pt = sd_pt + ni * NTC;
        const float* c_ss_fp = ss_fp + ci * NFC;  float* n_ss_fp = ss_fp + ni * NFC;
        const float* c_sd_pf = sd_pf + ci * NFC;  float* n_sd_pf = sd_pf + ni * NFC;

        if (!actor) {
            // merged: job A = t-dst (edge pt, src p), job B = f-dst (edge pf, src p)
            gat_tf<<<NTC / 64 + NFC / 64, 512>>>(NTC / 64,
                rp_pt, cs_pt, c_ss_pt, c_sd_pt, xpi, Wl + 0 * 4096, bl + 0 * 64, xto,
                nwsv + 1 * 64, n_ss_tp, nwdv + 0 * 64, n_sd_pt,
                rp_pf, cs_pf, c_ss_pf, c_sd_pf, xpi, Wl + 2 * 4096, bl + 2 * 64, xfo,
                nwsv + 3 * 64, n_ss_fp, nwdv + 2 * 64, n_sd_pf,
                relu);
            // p-dst: tp (src t OLD) + fp (src f OLD)
            gat_p<<<NPC / 32, 512>>>(
                rp_tp, cs_tp, c_ss_tp, c_sd_tp, xti, Wl + 1 * 4096, bl + 1 * 64,
                rp_fp, cs_fp, c_ss_fp, c_sd_fp, xfi, Wl + 3 * 4096, bl + 3 * 64,
                xp, relu,
                nwsv + 0 * 64, n_ss_pt, nwsv + 2 * 64, n_ss_pf,
                nwdv + 1 * 64, n_sd_tp, nwdv + 3 * 64, n_sd_fp);
        } else {
            gat_p<<<NPC / 32, 512>>>(
                rp_tp, cs_tp, c_ss_tp, c_sd_tp, xti, Wl + 1 * 4096, bl + 1 * 64,
                rp_fp, cs_fp, c_ss_fp, c_sd_fp, xfi, Wl + 3 * 4096, bl + 3 * 64,
                ap, 0,
                nullptr, nullptr, nullptr, nullptr,
                nullptr, nullptr, nullptr, nullptr);
        }
    }

    // pooling over final x: layer 3 wrote xt/xf parity 1; xp in place
    pool_k<<<BC, 256>>>(xp, 64, rep, 0);
    pool_k<<<BC, 256>>>(xt + (size_t)NTC * 64, 512, rep, 192);
    pool_k<<<BC, 256>>>(xf + (size_t)NFC * 64, 512, rep, 384);

    // actor head
    ln_ra<<<(NPC * 32) / 256, 256>>>(ap, ln_g, ln_b, outaW, outab, ra);
    act_softmax<<<BC, 64>>>(ra, part_id, out);

    // value head
    mlp_k<<<BC, 64>>>(rep, 576, innW, innb, h1);
    mlp_k<<<BC, 64>>>(h1, 64, fulW, fulb, h2);
    mlp_out<<<(BC * 32) / 256, 256>>>(h2, outW, outb, out + BC * 128);
}

// round 8
// speedup vs baseline: 1.6640x; 1.4102x over previous
#include <cuda_runtime.h>
#include <math.h>

#define NPC 16384
#define NTC 131072
#define NFC 131072
#define EC  262144
#define BC  256
#define FULLMASK 0xffffffffu

// ---------------- device scratch ----------------
__device__ float g_xp[NPC * 64];
__device__ float g_xt[2][NTC * 64];     // ping-pong
__device__ float g_xf[2][NFC * 64];
__device__ float g_ap[NPC * 64];
__device__ float g_hs0[NPC * 64];       // xp @ W[pt]
__device__ float g_hs1[NPC * 64];       // xp @ W[pf]
__device__ float g_ss_pt[2][NPC], g_ss_pf[2][NPC], g_sd_tp[2][NPC], g_sd_fp[2][NPC];
__device__ float g_ss_tp[2][NTC], g_sd_pt[2][NTC];
__device__ float g_ss_fp[2][NFC], g_sd_pf[2][NFC];
__device__ float g_wsv[5 * 4 * 64], g_wdv[5 * 4 * 64];
__device__ int g_rp_pt[NTC + 1], g_rp_pf[NFC + 1];
__device__ int g_rp_tp[NPC + 1], g_rp_fp[NPC + 1];
__device__ int g_cs_pt[EC], g_cs_tp[EC], g_cs_pf[EC], g_cs_fp[EC];
__device__ int g_cnt[4 * NTC];
__device__ float g_ra[NPC * 2];
__device__ float g_rep[BC * 576];
__device__ float g_h1[BC * 64], g_h2[BC * 64];

// ---------------- batched CSR build ----------------
__global__ void zero4(int* c) {
    int i = blockIdx.x * blockDim.x + threadIdx.x;
    if (i < 4 * NTC) c[i] = 0;
}

__global__ void hist4(const int* __restrict__ d0, const int* __restrict__ d1,
                      const int* __restrict__ d2, const int* __restrict__ d3,
                      int* __restrict__ cnt) {
    int t = blockIdx.y;
    const int* d = (t == 0) ? d0 : (t == 1) ? d1 : (t == 2) ? d2 : d3;
    int* c = cnt + t * NTC;
    int i = blockIdx.x * blockDim.x + threadIdx.x;
    if (i < EC) atomicAdd(&c[d[i]], 1);
}

__device__ void scan_body(const int* __restrict__ deg, int* __restrict__ rowptr,
                          int* __restrict__ rezero, int n) {
    __shared__ int warp_sums[32];
    __shared__ int s_carry;
    int tid = threadIdx.x;
    int lane = tid & 31, wid = tid >> 5;
    if (tid == 0) s_carry = 0;
    __syncthreads();
    for (int base = 0; base < n; base += 1024) {
        int i = base + tid;
        int v = (i < n) ? deg[i] : 0;
        int x = v;
        #pragma unroll
        for (int off = 1; off < 32; off <<= 1) {
            int y = __shfl_up_sync(FULLMASK, x, off);
            if (lane >= off) x += y;
        }
        if (lane == 31) warp_sums[wid] = x;
        __syncthreads();
        if (tid < 32) {
            int s = warp_sums[tid];
            #pragma unroll
            for (int off = 1; off < 32; off <<= 1) {
                int y = __shfl_up_sync(FULLMASK, s, off);
                if (tid >= off) s += y;
            }
            warp_sums[tid] = s;
        }
        __syncthreads();
        int incl = x + (wid ? warp_sums[wid - 1] : 0);
        if (i < n) { rowptr[i] = s_carry + incl - v; rezero[i] = 0; }
        int chunk_total = warp_sums[31];
        __syncthreads();
        if (tid == 0) s_carry += chunk_total;
        __syncthreads();
    }
    if (tid == 0) rowptr[n] = s_carry;
}

__global__ void scan4(int* __restrict__ cnt,
                      int* rp0, int* rp1, int* rp2, int* rp3) {
    int t = blockIdx.x;
    int* rp = (t == 0) ? rp0 : (t == 1) ? rp1 : (t == 2) ? rp2 : rp3;
    int n = (t == 0) ? NTC : (t == 1) ? NPC : (t == 2) ? NFC : NPC;
    scan_body(cnt + t * NTC, rp, cnt + t * NTC, n);
}

__global__ void scatter4(const int* __restrict__ s0, const int* __restrict__ d0,
                         const int* __restrict__ s1, const int* __restrict__ d1,
                         const int* __restrict__ s2, const int* __restrict__ d2,
                         const int* __restrict__ s3, const int* __restrict__ d3,
                         const int* rp0, const int* rp1, const int* rp2, const int* rp3,
                         int* __restrict__ cnt,
                         int* c0, int* c1, int* c2, int* c3) {
    int t = blockIdx.y;
    const int* src = (t == 0) ? s0 : (t == 1) ? s1 : (t == 2) ? s2 : s3;
    const int* dst = (t == 0) ? d0 : (t == 1) ? d1 : (t == 2) ? d2 : d3;
    const int* rp  = (t == 0) ? rp0 : (t == 1) ? rp1 : (t == 2) ? rp2 : rp3;
    int* csr = (t == 0) ? c0 : (t == 1) ? c1 : (t == 2) ? c2 : c3;
    int* cur = cnt + t * NTC;
    int i = blockIdx.x * blockDim.x + threadIdx.x;
    if (i >= EC) return;
    int d = dst[i];
    int pos = rp[d] + atomicAdd(&cur[d], 1);
    csr[pos] = src[i];
}

// ---------------- score vectors for ALL layers ----------------
__global__ void vec_all(const float* __restrict__ Ws, const float* __restrict__ as,
                        const float* __restrict__ Wd, const float* __restrict__ ad,
                        float* __restrict__ wsv, float* __restrict__ wdv) {
    int idx = blockIdx.x * blockDim.x + threadIdx.x;
    if (idx >= 2 * 5 * 4 * 64) return;
    int which = idx >= 1280;
    int r = which ? idx - 1280 : idx;
    int i = r & 63, lt = r >> 6;
    const float* W = which ? Wd : Ws;
    const float* a = which ? ad : as;
    float* o = which ? wdv : wsv;
    float acc = 0.f;
    const float* wr = W + (size_t)(lt * 64 + i) * 64;
    const float* ar = a + lt * 64;
    #pragma unroll 8
    for (int j = 0; j < 64; j++) acc = fmaf(wr[j], ar[j], acc);
    o[r] = acc;
}

// ---------------- embed ----------------
__global__ void embed_k(const float* __restrict__ mass, const int* __restrict__ pstate,
                        const float* __restrict__ embW, const float* __restrict__ embS,
                        float* __restrict__ xp) {
    int idx = blockIdx.x * blockDim.x + threadIdx.x;
    if (idx >= NPC * 64) return;
    int n = idx >> 6, j = idx & 63;
    float v;
    if (j < 32) v = mass[n] * embW[j];
    else {
        int st = pstate[2 * n] + 2 * pstate[2 * n + 1];
        v = embS[st * 32 + (j - 32)];
    }
    xp[idx] = v;
}

// ---------------- up to 4 per-row dot products (layer-0 init) ----------------
__global__ void dot4(const float* __restrict__ X, int n,
                     const float* v0, float* o0, const float* v1, float* o1,
                     const float* v2, float* o2, const float* v3, float* o3) {
    int idx = blockIdx.x * blockDim.x + threadIdx.x;
    int w = idx >> 5;
    if (w >= n) return;
    int lane = idx & 31;
    float2 x = *(const float2*)&X[(size_t)w * 64 + lane * 2];
#define DODOT(v, o) if (v) { \
        float s = x.x * v[2 * lane] + x.y * v[2 * lane + 1]; \
        for (int off = 16; off; off >>= 1) s += __shfl_xor_sync(FULLMASK, s, off); \
        if (lane == 0) o[w] = s; }
    DODOT(v0, o0)
    DODOT(v1, o1)
    DODOT(v2, o2)
    DODOT(v3, o3)
#undef DODOT
}

// ---------------- hs matmul: hs0 = X@W0, hs1 = X@W1 (blockIdx split) ----------------
__global__ void __launch_bounds__(256) mm_hs(const float* __restrict__ X,
                                             const float* __restrict__ W0, float* __restrict__ Y0,
                                             const float* __restrict__ W1, float* __restrict__ Y1) {
    __shared__ float Xs[64][65];
    __shared__ float Wsh[64][68];
    int half = blockIdx.x >= (NPC / 64);
    int row0 = (half ? blockIdx.x - NPC / 64 : blockIdx.x) * 64;
    const float* W = half ? W1 : W0;
    float* Y = half ? Y1 : Y0;
    int tid = threadIdx.x;
    const float4* W4 = (const float4*)W;
    for (int i = tid; i < 1024; i += 256) {
        float4 v = W4[i];
        int r = i >> 4, c = (i & 15) * 4;
        Wsh[r][c] = v.x; Wsh[r][c + 1] = v.y; Wsh[r][c + 2] = v.z; Wsh[r][c + 3] = v.w;
    }
    const float4* X4 = (const float4*)(X + (size_t)row0 * 64);
    for (int i = tid; i < 1024; i += 256) {
        float4 v = X4[i];
        int r = i >> 4, c = (i & 15) * 4;
        Xs[r][c] = v.x; Xs[r][c + 1] = v.y; Xs[r][c + 2] = v.z; Xs[r][c + 3] = v.w;
    }
    __syncthreads();
    int tx = tid & 15, ty = tid >> 4;
    int c0 = tx * 4, r0 = ty * 4;
    float acc[4][4] = {};
    #pragma unroll
    for (int k = 0; k < 64; k++) {
        float4 w = *(const float4*)&Wsh[k][c0];
        float x0 = Xs[r0][k], x1 = Xs[r0 + 1][k], x2 = Xs[r0 + 2][k], x3 = Xs[r0 + 3][k];
        acc[0][0] = fmaf(x0, w.x, acc[0][0]); acc[0][1] = fmaf(x0, w.y, acc[0][1]);
        acc[0][2] = fmaf(x0, w.z, acc[0][2]); acc[0][3] = fmaf(x0, w.w, acc[0][3]);
        acc[1][0] = fmaf(x1, w.x, acc[1][0]); acc[1][1] = fmaf(x1, w.y, acc[1][1]);
        acc[1][2] = fmaf(x1, w.z, acc[1][2]); acc[1][3] = fmaf(x1, w.w, acc[1][3]);
        acc[2][0] = fmaf(x2, w.x, acc[2][0]); acc[2][1] = fmaf(x2, w.y, acc[2][1]);
        acc[2][2] = fmaf(x2, w.z, acc[2][2]); acc[2][3] = fmaf(x2, w.w, acc[2][3]);
        acc[3][0] = fmaf(x3, w.x, acc[3][0]); acc[3][1] = fmaf(x3, w.y, acc[3][1]);
        acc[3][2] = fmaf(x3, w.z, acc[3][2]); acc[3][3] = fmaf(x3, w.w, acc[3][3]);
    }
    #pragma unroll
    for (int i = 0; i < 4; i++)
        *(float4*)&Y[((size_t)(row0 + r0 + i)) * 64 + c0] =
            make_float4(acc[i][0], acc[i][1], acc[i][2], acc[i][3]);
}

// ---------------- t/f aggregation: out = softmax-agg(hs) + b; no matmul, no smem ----------------
// 4-lane groups, one dst row each; two-pass softmax, per-lane redundant score loads (L1 broadcast).
__global__ void __launch_bounds__(512) agg_tf(int nA,
        const int* rpA, const int* csA, const float* ssA, const float* sdA,
        const float* hsA, const float* bA, float* YA,
        const float* vA0, float* oA0, const float* vA1, float* oA1,
        const int* rpB, const int* csB, const float* ssB, const float* sdB,
        const float* hsB, const float* bB, float* YB,
        const float* vB0, float* oB0, const float* vB1, float* oB1,
        int relu) {
    bool isA = (int)blockIdx.x < nA;
    int row0 = (isA ? blockIdx.x : blockIdx.x - nA) * 128;
    const int* rp = isA ? rpA : rpB;
    const int* cs = isA ? csA : csB;
    const float* ss = isA ? ssA : ssB;
    const float* sd = isA ? sdA : sdB;
    const float* hs = isA ? hsA : hsB;
    const float* b = isA ? bA : bB;
    float* Y = isA ? YA : YB;
    const float* v0 = isA ? vA0 : vB0;  float* o0 = isA ? oA0 : oB0;
    const float* v1 = isA ? vA1 : vB1;  float* o1 = isA ? oA1 : oB1;

    int tid = threadIdx.x;
    int g = tid >> 2, gl = tid & 3;
    int d = row0 + g;
    int beg = rp[d], end = rp[d + 1];
    float sdv = sd[d];
    // pass 1: max
    float m = -1e30f;
    for (int j = beg; j < end; j++) {
        float t = ss[cs[j]] + sdv;
        t = t > 0.f ? t : 0.2f * t;
        m = fmaxf(m, t);
    }
    // pass 2: exp-sum + gather
    float s = 0.f;
    float4 a0 = {0,0,0,0}, a1 = {0,0,0,0}, a2 = {0,0,0,0}, a3 = {0,0,0,0};
    const float4* H4 = (const float4*)hs;
    for (int j = beg; j < end; j++) {
        int src = cs[j];
        float t = ss[src] + sdv;
        t = t > 0.f ? t : 0.2f * t;
        float ex = __expf(t - m);
        s += ex;
        size_t base = (size_t)src * 16 + gl * 4;
        float4 h0 = H4[base], h1 = H4[base + 1], h2 = H4[base + 2], h3 = H4[base + 3];
        a0.x = fmaf(ex, h0.x, a0.x); a0.y = fmaf(ex, h0.y, a0.y);
        a0.z = fmaf(ex, h0.z, a0.z); a0.w = fmaf(ex, h0.w, a0.w);
        a1.x = fmaf(ex, h1.x, a1.x); a1.y = fmaf(ex, h1.y, a1.y);
        a1.z = fmaf(ex, h1.z, a1.z); a1.w = fmaf(ex, h1.w, a1.w);
        a2.x = fmaf(ex, h2.x, a2.x); a2.y = fmaf(ex, h2.y, a2.y);
        a2.z = fmaf(ex, h2.z, a2.z); a2.w = fmaf(ex, h2.w, a2.w);
        a3.x = fmaf(ex, h3.x, a3.x); a3.y = fmaf(ex, h3.y, a3.y);
        a3.z = fmaf(ex, h3.z, a3.z); a3.w = fmaf(ex, h3.w, a3.w);
    }
    float inv = s > 0.f ? 1.f / s : 0.f;
    const float4* B4 = (const float4*)b;
    float4 bb0 = B4[gl * 4], bb1 = B4[gl * 4 + 1], bb2 = B4[gl * 4 + 2], bb3 = B4[gl * 4 + 3];
    float4 ot[4];
    ot[0] = make_float4(a0.x * inv + bb0.x, a0.y * inv + bb0.y, a0.z * inv + bb0.z, a0.w * inv + bb0.w);
    ot[1] = make_float4(a1.x * inv + bb1.x, a1.y * inv + bb1.y, a1.z * inv + bb1.z, a1.w * inv + bb1.w);
    ot[2] = make_float4(a2.x * inv + bb2.x, a2.y * inv + bb2.y, a2.z * inv + bb2.z, a2.w * inv + bb2.w);
    ot[3] = make_float4(a3.x * inv + bb3.x, a3.y * inv + bb3.y, a3.z * inv + bb3.z, a3.w * inv + bb3.w);
    if (relu) {
        #pragma unroll
        for (int q = 0; q < 4; q++) {
            ot[q].x = fmaxf(ot[q].x, 0.f); ot[q].y = fmaxf(ot[q].y, 0.f);
            ot[q].z = fmaxf(ot[q].z, 0.f); ot[q].w = fmaxf(ot[q].w, 0.f);
        }
    }
    float4* Yr = (float4*)&Y[(size_t)d * 64];
    #pragma unroll
    for (int q = 0; q < 4; q++) Yr[gl * 4 + q] = ot[q];
    // epilogue dots (next-layer scores)
#define DOT(v, o) { \
        const float4* V4 = (const float4*)v; \
        float dd = 0.f; \
        _Pragma("unroll") \
        for (int q = 0; q < 4; q++) { \
            float4 vv = V4[gl * 4 + q]; \
            dd += ot[q].x * vv.x + ot[q].y * vv.y + ot[q].z * vv.z + ot[q].w * vv.w; \
        } \
        dd += __shfl_xor_sync(FULLMASK, dd, 1); \
        dd += __shfl_xor_sync(FULLMASK, dd, 2); \
        if (gl == 0) o[d] = dd; }
    DOT(v0, o0)
    DOT(v1, o1)
#undef DOT
}

// ---------------- p-dst: two-pass softmax-agg into smem -> two matmuls -> out + dots ----------------
__global__ void __launch_bounds__(256) gat_p(
        const int* rp1, const int* cs1, const float* ss1, const float* sd1,
        const float* X1, const float* W1,
        const int* rp2, const int* cs2, const float* ss2, const float* sd2,
        const float* X2, const float* W2,
        const float* b1, const float* b2,
        float* __restrict__ Y, int relu,
        const float* v0, float* o0, const float* v1, float* o1,
        const float* v2, float* o2, const float* v3, float* o3) {
    __shared__ float Zs[64 * 68];
    __shared__ float Wsh[64][68];
    int row0 = blockIdx.x * 64;
    int tid = threadIdx.x;
    int g = tid >> 2, gl = tid & 3;
    int tx = tid & 15, ty = tid >> 4;
    int c0 = tx * 4, r0 = ty * 4;
    float acc[4][4] = {};
    int d = row0 + g;
    for (int p = 0; p < 2; p++) {
        const int* rp = p ? rp2 : rp1;
        const int* cs = p ? cs2 : cs1;
        const float* ss = p ? ss2 : ss1;
        const float* sd = p ? sd2 : sd1;
        const float* X = p ? X2 : X1;
        const float* W = p ? W2 : W1;
        const float4* W4 = (const float4*)W;
        for (int i = tid; i < 1024; i += 256) {
            float4 v = W4[i];
            int r = i >> 4, c = (i & 15) * 4;
            Wsh[r][c] = v.x; Wsh[r][c + 1] = v.y; Wsh[r][c + 2] = v.z; Wsh[r][c + 3] = v.w;
        }
        // phase 1: aggregate row d with 4 lanes
        int beg = rp[d], end = rp[d + 1];
        float sdv = sd[d];
        float m = -1e30f;
        for (int j = beg; j < end; j++) {
            float t = ss[cs[j]] + sdv;
            t = t > 0.f ? t : 0.2f * t;
            m = fmaxf(m, t);
        }
        float s = 0.f;
        float4 a0 = {0,0,0,0}, a1 = {0,0,0,0}, a2 = {0,0,0,0}, a3 = {0,0,0,0};
        const float4* X4 = (const float4*)X;
        for (int j = beg; j < end; j++) {
            int src = cs[j];
            float t = ss[src] + sdv;
            t = t > 0.f ? t : 0.2f * t;
            float ex = __expf(t - m);
            s += ex;
            size_t base = (size_t)src * 16 + gl * 4;
            float4 h0 = X4[base], h1 = X4[base + 1], h2 = X4[base + 2], h3 = X4[base + 3];
            a0.x = fmaf(ex, h0.x, a0.x); a0.y = fmaf(ex, h0.y, a0.y);
            a0.z = fmaf(ex, h0.z, a0.z); a0.w = fmaf(ex, h0.w, a0.w);
            a1.x = fmaf(ex, h1.x, a1.x); a1.y = fmaf(ex, h1.y, a1.y);
            a1.z = fmaf(ex, h1.z, a1.z); a1.w = fmaf(ex, h1.w, a1.w);
            a2.x = fmaf(ex, h2.x, a2.x); a2.y = fmaf(ex, h2.y, a2.y);
            a2.z = fmaf(ex, h2.z, a2.z); a2.w = fmaf(ex, h2.w, a2.w);
            a3.x = fmaf(ex, h3.x, a3.x); a3.y = fmaf(ex, h3.y, a3.y);
            a3.z = fmaf(ex, h3.z, a3.z); a3.w = fmaf(ex, h3.w, a3.w);
        }
        float inv = s > 0.f ? 1.f / s : 0.f;
        float4* Zr = (float4*)&Zs[g * 68];
        Zr[gl * 4]     = make_float4(a0.x * inv, a0.y * inv, a0.z * inv, a0.w * inv);
        Zr[gl * 4 + 1] = make_float4(a1.x * inv, a1.y * inv, a1.z * inv, a1.w * inv);
        Zr[gl * 4 + 2] = make_float4(a2.x * inv, a2.y * inv, a2.z * inv, a2.w * inv);
        Zr[gl * 4 + 3] = make_float4(a3.x * inv, a3.y * inv, a3.z * inv, a3.w * inv);
        __syncthreads();
        // phase 2: acc += Zs @ W
        #pragma unroll
        for (int k = 0; k < 64; k++) {
            float4 wv = *(const float4*)&Wsh[k][c0];
            float x0 = Zs[r0 * 68 + k], x1 = Zs[(r0 + 1) * 68 + k];
            float x2 = Zs[(r0 + 2) * 68 + k], x3 = Zs[(r0 + 3) * 68 + k];
            acc[0][0] = fmaf(x0, wv.x, acc[0][0]); acc[0][1] = fmaf(x0, wv.y, acc[0][1]);
            acc[0][2] = fmaf(x0, wv.z, acc[0][2]); acc[0][3] = fmaf(x0, wv.w, acc[0][3]);
            acc[1][0] = fmaf(x1, wv.x, acc[1][0]); acc[1][1] = fmaf(x1, wv.y, acc[1][1]);
            acc[1][2] = fmaf(x1, wv.z, acc[1][2]); acc[1][3] = fmaf(x1, wv.w, acc[1][3]);
            acc[2][0] = fmaf(x2, wv.x, acc[2][0]); acc[2][1] = fmaf(x2, wv.y, acc[2][1]);
            acc[2][2] = fmaf(x2, wv.z, acc[2][2]); acc[2][3] = fmaf(x2, wv.w, acc[2][3]);
            acc[3][0] = fmaf(x3, wv.x, acc[3][0]); acc[3][1] = fmaf(x3, wv.y, acc[3][1]);
            acc[3][2] = fmaf(x3, wv.z, acc[3][2]); acc[3][3] = fmaf(x3, wv.w, acc[3][3]);
        }
        __syncthreads();
    }
    // bias + relu, stage to Zs for coalesced out + dots
    #pragma unroll
    for (int i = 0; i < 4; i++)
        #pragma unroll
        for (int c = 0; c < 4; c++) {
            float v = acc[i][c] + b1[c0 + c] + b2[c0 + c];
            if (relu) v = fmaxf(v, 0.f);
            Zs[(r0 + i) * 68 + c0 + c] = v;
        }
    __syncthreads();
    float4 ot[4];
    const float4* Zr = (const float4*)&Zs[g * 68];
    #pragma unroll
    for (int q = 0; q < 4; q++) ot[q] = Zr[gl * 4 + q];
    float4* Yr = (float4*)&Y[(size_t)d * 64];
    #pragma unroll
    for (int q = 0; q < 4; q++) Yr[gl * 4 + q] = ot[q];
#define DOT(v, o) if (v) { \
        const float4* V4 = (const float4*)v; \
        float dd = 0.f; \
        _Pragma("unroll") \
        for (int q = 0; q < 4; q++) { \
            float4 vv = V4[gl * 4 + q]; \
            dd += ot[q].x * vv.x + ot[q].y * vv.y + ot[q].z * vv.z + ot[q].w * vv.w; \
        } \
        dd += __shfl_xor_sync(FULLMASK, dd, 1); \
        dd += __shfl_xor_sync(FULLMASK, dd, 2); \
        if (gl == 0) o[d] = dd; }
    DOT(v0, o0)
    DOT(v1, o1)
    DOT(v2, o2)
    DOT(v3, o3)
#undef DOT
}

// ---------------- pooling ----------------
__global__ void pool_k(const float* __restrict__ x, int npg, float* __restrict__ rep, int off) {
    int b = blockIdx.x;
    int t = threadIdx.x;            // 256
    int d = t & 63, c = t >> 6;
    const float* base = x + (size_t)b * npg * 64;
    float mx = -1e30f, mn = 1e30f, sm = 0.f;
    for (int n = c; n < npg; n += 4) {
        float v = base[(size_t)n * 64 + d];
        mx = fmaxf(mx, v); mn = fminf(mn, v); sm += v;
    }
    __shared__ float smx[4][64], smn[4][64], ssm[4][64];
    smx[c][d] = mx; smn[c][d] = mn; ssm[c][d] = sm;
    __syncthreads();
    if (c == 0) {
        for (int i = 1; i < 4; i++) {
            mx = fmaxf(mx, smx[i][d]); mn = fminf(mn, smn[i][d]); sm += ssm[i][d];
        }
        rep[b * 576 + off + d] = mx;
        rep[b * 576 + off + 64 + d] = mn;
        rep[b * 576 + off + 128 + d] = sm / (float)npg;
    }
}

// ---------------- LayerNorm + out_a projection ----------------
__global__ void ln_ra(const float* __restrict__ ap, const float* __restrict__ g,
                      const float* __restrict__ be, const float* __restrict__ Wa,
                      const float* __restrict__ ba, float* __restrict__ ra) {
    int idx = blockIdx.x * blockDim.x + threadIdx.x;
    int n = idx >> 5;
    if (n >= NPC) return;
    int lane = idx & 31;
    float2 v = *(const float2*)&ap[(size_t)n * 64 + lane * 2];
    float sum = v.x + v.y;
    for (int o = 16; o; o >>= 1) sum += __shfl_xor_sync(FULLMASK, sum, o);
    float mu = sum * (1.f / 64.f);
    float dx = v.x - mu, dy = v.y - mu;
    float vs = dx * dx + dy * dy;
    for (int o = 16; o; o >>= 1) vs += __shfl_xor_sync(FULLMASK, vs, o);
    float rs = rsqrtf(vs * (1.f / 64.f) + 1e-5f);
    float y0 = dx * rs * g[2 * lane] + be[2 * lane];
    float y1 = dy * rs * g[2 * lane + 1] + be[2 * lane + 1];
    float r0 = y0 * Wa[(2 * lane) * 2]     + y1 * Wa[(2 * lane + 1) * 2];
    float r1 = y0 * Wa[(2 * lane) * 2 + 1] + y1 * Wa[(2 * lane + 1) * 2 + 1];
    for (int o = 16; o; o >>= 1) r0 += __shfl_xor_sync(FULLMASK, r0, o);
    for (int o = 16; o; o >>= 1) r1 += __shfl_xor_sync(FULLMASK, r1, o);
    if (lane == 0) {
        ra[2 * n]     = r0 + ba[0];
        ra[2 * n + 1] = r1 + ba[1];
    }
}

// ---------------- per-graph softmax + scatter to actions ----------------
__device__ __forceinline__ float blk64_max(float v, volatile float* sh) {
    for (int o = 16; o; o >>= 1) v = fmaxf(v, __shfl_xor_sync(FULLMASK, v, o));
    if ((threadIdx.x & 31) == 0) sh[threadIdx.x >> 5] = v;
    __syncthreads();
    float r = fmaxf(sh[0], sh[1]);
    __syncthreads();
    return r;
}
__device__ __forceinline__ float blk64_sum(float v, volatile float* sh) {
    for (int o = 16; o; o >>= 1) v += __shfl_xor_sync(FULLMASK, v, o);
    if ((threadIdx.x & 31) == 0) sh[threadIdx.x >> 5] = v;
    __syncthreads();
    float r = sh[0] + sh[1];
    __syncthreads();
    return r;
}

__global__ void act_softmax(const float* __restrict__ ra, const int* __restrict__ part_id,
                            float* __restrict__ out) {
    __shared__ float sh[2];
    int b = blockIdx.x, t = threadIdx.x;        // 64
    int n = b * 64 + t;
    float v0 = ra[2 * n], v1 = ra[2 * n + 1];
    float m0 = blk64_max(v0, sh);
    float m1 = blk64_max(v1, sh);
    float e0 = expf(v0 - m0), e1 = expf(v1 - m1);
    float s0 = blk64_sum(e0, sh);
    float s1 = blk64_sum(e1, sh);
    int p = part_id[n];
    out[b * 128 + p] = e0 / s0;
    out[b * 128 + 64 + p] = e1 / s1;
}

// ---------------- value head MLPs ----------------
__global__ void mlp_k(const float* __restrict__ in, int K, const float* __restrict__ W,
                      const float* __restrict__ bias, float* __restrict__ out) {
    __shared__ float s[576];
    int b = blockIdx.x, j = threadIdx.x;        // 64
    for (int k = j; k < K; k += 64) s[k] = in[b * K + k];
    __syncthreads();
    float acc = bias[j];
    for (int k = 0; k < K; k++) acc = fmaf(s[k], W[k * 64 + j], acc);
    acc = 0.5f * acc * (1.f + erff(acc * 0.70710678118654752f));
    out[b * 64 + j] = acc;
}

__global__ void mlp_out(const float* __restrict__ h, const float* __restrict__ Wo,
                        const float* __restrict__ bo, float* __restrict__ V) {
    int idx = blockIdx.x * blockDim.x + threadIdx.x;
    int b = idx >> 5;
    if (b >= BC) return;
    int lane = idx & 31;
    float2 v = *(const float2*)&h[b * 64 + lane * 2];
    float s = v.x * Wo[2 * lane] + v.y * Wo[2 * lane + 1];
    for (int o = 16; o; o >>= 1) s += __shfl_xor_sync(FULLMASK, s, o);
    if (lane == 0) V[b] = tanhf(s + bo[0]);
}

// ---------------- host ----------------
#define SYMF(p, s) do { void* _q; cudaGetSymbolAddress(&_q, s); p = (float*)_q; } while (0)
#define SYMI(p, s) do { void* _q; cudaGetSymbolAddress(&_q, s); p = (int*)_q; } while (0)

extern "C" void kernel_launch(void* const* d_in, const int* in_sizes, int n_in,
                              void* d_out, int out_size) {
    const float* mass      = (const float*)d_in[0];
    const int*   pstate    = (const int*)d_in[1];
    const float* torque_x  = (const float*)d_in[2];
    const float* force_x   = (const float*)d_in[3];
    const int* e_pt_src = (const int*)d_in[4];
    const int* e_pt_dst = (const int*)d_in[5];
    const int* e_tp_src = (const int*)d_in[6];
    const int* e_tp_dst = (const int*)d_in[7];
    const int* e_pf_src = (const int*)d_in[8];
    const int* e_pf_dst = (const int*)d_in[9];
    const int* e_fp_src = (const int*)d_in[10];
    const int* e_fp_dst = (const int*)d_in[11];
    const int* part_id  = (const int*)d_in[13];
    const float* embW   = (const float*)d_in[14];
    const float* embS   = (const float*)d_in[15];
    const float* W_src  = (const float*)d_in[16];
    const float* W_dst  = (const float*)d_in[17];
    const float* a_src  = (const float*)d_in[18];
    const float* a_dst  = (const float*)d_in[19];
    const float* b_conv = (const float*)d_in[20];
    const float* ln_g   = (const float*)d_in[21];
    const float* ln_b   = (const float*)d_in[22];
    const float* outaW  = (const float*)d_in[23];
    const float* outab  = (const float*)d_in[24];
    const float* innW   = (const float*)d_in[25];
    const float* innb   = (const float*)d_in[26];
    const float* fulW   = (const float*)d_in[27];
    const float* fulb   = (const float*)d_in[28];
    const float* outW   = (const float*)d_in[29];
    const float* outb   = (const float*)d_in[30];
    float* out = (float*)d_out;

    float *xp, *xt, *xf, *ap, *hs0, *hs1;
    float *ss_pt, *ss_pf, *sd_tp, *sd_fp, *ss_tp, *sd_pt, *ss_fp, *sd_pf;
    float *wsv, *wdv, *ra, *rep, *h1, *h2;
    int *rp_pt, *rp_pf, *rp_tp, *rp_fp, *cs_pt, *cs_tp, *cs_pf, *cs_fp, *cnt;
    SYMF(xp, g_xp); SYMF(xt, g_xt); SYMF(xf, g_xf); SYMF(ap, g_ap);
    SYMF(hs0, g_hs0); SYMF(hs1, g_hs1);
    SYMF(ss_pt, g_ss_pt); SYMF(ss_pf, g_ss_pf); SYMF(sd_tp, g_sd_tp); SYMF(sd_fp, g_sd_fp);
    SYMF(ss_tp, g_ss_tp); SYMF(sd_pt, g_sd_pt); SYMF(ss_fp, g_ss_fp); SYMF(sd_pf, g_sd_pf);
    SYMF(wsv, g_wsv); SYMF(wdv, g_wdv); SYMF(ra, g_ra);
    SYMF(rep, g_rep); SYMF(h1, g_h1); SYMF(h2, g_h2);
    SYMI(rp_pt, g_rp_pt); SYMI(rp_pf, g_rp_pf); SYMI(rp_tp, g_rp_tp); SYMI(rp_fp, g_rp_fp);
    SYMI(cs_pt, g_cs_pt); SYMI(cs_tp, g_cs_tp); SYMI(cs_pf, g_cs_pf); SYMI(cs_fp, g_cs_fp);
    SYMI(cnt, g_cnt);

    // batched CSR build
    zero4<<<(4 * NTC) / 256, 256>>>(cnt);
    { dim3 g(EC / 256, 4); hist4<<<g, 256>>>(e_pt_dst, e_tp_dst, e_pf_dst, e_fp_dst, cnt); }
    scan4<<<4, 1024>>>(cnt, rp_pt, rp_tp, rp_pf, rp_fp);
    { dim3 g(EC / 256, 4);
      scatter4<<<g, 256>>>(e_pt_src, e_pt_dst, e_tp_src, e_tp_dst,
                           e_pf_src, e_pf_dst, e_fp_src, e_fp_dst,
                           rp_pt, rp_tp, rp_pf, rp_fp, cnt,
                           cs_pt, cs_tp, cs_pf, cs_fp); }

    // score vectors; embed; layer-0 score dots (buffer 0)
    vec_all<<<10, 256>>>(W_src, a_src, W_dst, a_dst, wsv, wdv);
    dot4<<<(NTC * 32) / 256, 256>>>(torque_x, NTC,
         wsv + 1 * 64, ss_tp, wdv + 0 * 64, sd_pt, nullptr, nullptr, nullptr, nullptr);
    dot4<<<(NFC * 32) / 256, 256>>>(force_x, NFC,
         wsv + 3 * 64, ss_fp, wdv + 2 * 64, sd_pf, nullptr, nullptr, nullptr, nullptr);
    embed_k<<<(NPC * 64) / 256, 256>>>(mass, pstate, embW, embS, xp);
    dot4<<<(NPC * 32) / 256, 256>>>(xp, NPC,
         wsv + 0 * 64, ss_pt, wsv + 2 * 64, ss_pf,
         wdv + 1 * 64, sd_tp, wdv + 3 * 64, sd_fp);

    for (int l = 0; l < 5; l++) {
        const float* xti = (l == 0) ? torque_x : xt + (size_t)((l + 1) & 1) * NTC * 64;
        const float* xfi = (l == 0) ? force_x  : xf + (size_t)((l + 1) & 1) * NFC * 64;
        float* xto = xt + (size_t)(l & 1) * NTC * 64;
        float* xfo = xf + (size_t)(l & 1) * NFC * 64;
        const float* Wl = W_src + (size_t)l * 4 * 4096;
        const float* bl = b_conv + (size_t)l * 4 * 64;
        int relu = (l < 3) ? 1 : 0;
        int actor = (l == 4);
        const float* nwsv = wsv + (size_t)(l + 1) * 4 * 64;
        const float* nwdv = wdv + (size_t)(l + 1) * 4 * 64;
        int ci = l & 1, ni = (l + 1) & 1;
        const float* c_ss_pt = ss_pt + ci * NPC;  float* n_ss_pt = ss_pt + ni * NPC;
        const float* c_ss_pf = ss_pf + ci * NPC;  float* n_ss_pf = ss_pf + ni * NPC;
        const float* c_sd_tp = sd_tp + ci * NPC;  float* n_sd_tp = sd_tp + ni * NPC;
        const float* c_sd_fp = sd_fp + ci * NPC;  float* n_sd_fp = sd_fp + ni * NPC;
        const float* c_ss_tp = ss_tp + ci * NTC;  float* n_ss_tp = ss_tp + ni * NTC;
        const float* c_sd_pt = sd_pt + ci * NTC;  float* n_sd_pt = sd_pt + ni * NTC;
        const float* c_ss_fp = ss_fp + ci * NFC;  float* n_ss_fp = ss_fp + ni * NFC;
        const float* c_sd_pf = sd_pf + ci * NFC;  float* n_sd_pf = sd_pf + ni * NFC;

        if (!actor) {
            // transform-first for t/f dst: hs0 = xp@W[pt], hs1 = xp@W[pf]
            mm_hs<<<2 * (NPC / 64), 256>>>(xp, Wl + 0 * 4096, hs0, Wl + 2 * 4096, hs1);
            // aggregate hs directly into xt/xf (no per-dst matmul)
            agg_tf<<<NTC / 128 + NFC / 128, 512>>>(NTC / 128,
                rp_pt, cs_pt, c_ss_pt, c_sd_pt, hs0, bl + 0 * 64, xto,
                nwsv + 1 * 64, n_ss_tp, nwdv + 0 * 64, n_sd_pt,
                rp_pf, cs_pf, c_ss_pf, c_sd_pf, hs1, bl + 2 * 64, xfo,
                nwsv + 3 * 64, n_ss_fp, nwdv + 2 * 64, n_sd_pf,
                relu);
            // p-dst: aggregate-first from OLD xt/xf, then 2 small matmuls
            gat_p<<<NPC / 64, 256>>>(
                rp_tp, cs_tp, c_ss_tp, c_sd_tp, xti, Wl + 1 * 4096,
                rp_fp, cs_fp, c_ss_fp, c_sd_fp, xfi, Wl + 3 * 4096,
                bl + 1 * 64, bl + 3 * 64,
                xp, relu,
                nwsv + 0 * 64, n_ss_pt, nwsv + 2 * 64, n_ss_pf,
                nwdv + 1 * 64, n_sd_tp, nwdv + 3 * 64, n_sd_fp);
        } else {
            gat_p<<<NPC / 64, 256>>>(
                rp_tp, cs_tp, c_ss_tp, c_sd_tp, xti, Wl + 1 * 4096,
                rp_fp, cs_fp, c_ss_fp, c_sd_fp, xfi, Wl + 3 * 4096,
                bl + 1 * 64, bl + 3 * 64,
                ap, 0,
                nullptr, nullptr, nullptr, nullptr,
                nullptr, nullptr, nullptr, nullptr);
        }
    }

    // pooling over final x: layer 3 wrote xt/xf parity 1; xp in place
    pool_k<<<BC, 256>>>(xp, 64, rep, 0);
    pool_k<<<BC, 256>>>(xt + (size_t)NTC * 64, 512, rep, 192);
    pool_k<<<BC, 256>>>(xf + (size_t)NFC * 64, 512, rep, 384);

    // actor head
    ln_ra<<<(NPC * 32) / 256, 256>>>(ap, ln_g, ln_b, outaW, outab, ra);
    act_softmax<<<BC, 64>>>(ra, part_id, out);

    // value head
    mlp_k<<<BC, 64>>>(rep, 576, innW, innb, h1);
    mlp_k<<<BC, 64>>>(h1, 64, fulW, fulb, h2);
    mlp_out<<<(BC * 32) / 256, 256>>>(h2, outW, outb, out + BC * 128);
}